// round 1
// baseline (speedup 1.0000x reference)
#include <cuda_runtime.h>

// Problem constants
#define BSZ   2
#define NTOK  2048          // T*F = 16*128
#define DIM   1024
#define NHEAD 16
#define HDIM  64

// Scratch: Q,K,V,O in (B, H, N, E) layout. 16 MiB each.
__device__ float g_Q[BSZ * NHEAD * NTOK * HDIM];
__device__ float g_K[BSZ * NHEAD * NTOK * HDIM];
__device__ float g_V[BSZ * NHEAD * NTOK * HDIM];
__device__ float g_O[BSZ * NHEAD * NTOK * HDIM];

// ---------------------------------------------------------------------------
// sgemm64: C[M=4096, N=1024] = A(row-major 4096x1024) * W^T
// W row j (length 1024) comes from Wlb[j] if j < split else Wla[j-split].
// SCATTER=true  -> store to (B,H,N,E) layout (projection epilogue)
// SCATTER=false -> store plain row-major (final output projection)
// 64x64 tile, 256 threads, 4x4 microtile, BK=16.
// ---------------------------------------------------------------------------
template <bool SCATTER>
__global__ void __launch_bounds__(256)
sgemm64(const float* __restrict__ A,
        const float* __restrict__ Wlb,
        const float* __restrict__ Wla,
        int split,
        float* __restrict__ Cout) {
    __shared__ float As[16][68];   // [k][m], padded: 16B-aligned float4 rows
    __shared__ float Bs[16][68];   // [k][n]

    const int tile_n = blockIdx.x;     // 0..15
    const int tile_m = blockIdx.y;     // 0..63
    const int tid    = threadIdx.x;    // 0..255
    const int row0   = tile_m * 64;
    const int col0   = tile_n * 64;
    const int tm     = (tid >> 4) << 2;   // 0..60
    const int tn     = (tid & 15) << 2;   // 0..60

    float acc[4][4] = {};

    for (int k0 = 0; k0 < DIM; k0 += 16) {
        // Load A tile: 64 rows x 16 k
        #pragma unroll
        for (int i = 0; i < 4; i++) {
            int idx = tid + i * 256;          // 0..1023
            int m = idx >> 4;
            int k = idx & 15;
            As[k][m] = A[(long)(row0 + m) * DIM + k0 + k];

            int j = col0 + m;                 // weight output row
            const float* W = (j < split) ? Wlb : Wla;
            int jj = (j < split) ? j : (j - split);
            Bs[k][m] = W[(long)jj * DIM + k0 + k];
        }
        __syncthreads();

        #pragma unroll
        for (int k = 0; k < 16; k++) {
            float4 a4 = *reinterpret_cast<const float4*>(&As[k][tm]);
            float4 b4 = *reinterpret_cast<const float4*>(&Bs[k][tn]);
            float a[4] = {a4.x, a4.y, a4.z, a4.w};
            float b[4] = {b4.x, b4.y, b4.z, b4.w};
            #pragma unroll
            for (int i = 0; i < 4; i++)
                #pragma unroll
                for (int j = 0; j < 4; j++)
                    acc[i][j] += a[i] * b[j];
        }
        __syncthreads();
    }

    #pragma unroll
    for (int i = 0; i < 4; i++) {
        int m = row0 + tm + i;               // global row = b*2048 + n
        if (SCATTER) {
            int b = m >> 11;
            int n = m & 2047;
            #pragma unroll
            for (int j = 0; j < 4; j++) {
                int c = col0 + tn + j;       // = h*64 + e
                int h = c >> 6;
                int e = c & 63;
                Cout[(((long)(b * NHEAD + h) * NTOK + n) * HDIM) + e] = acc[i][j];
            }
        } else {
            #pragma unroll
            for (int j = 0; j < 4; j++)
                Cout[(long)m * DIM + col0 + tn + j] = acc[i][j];
        }
    }
}

// ---------------------------------------------------------------------------
// Flash-style attention. One block per (qtile=64 rows, head, batch).
// Heads 0..7: causal (key <= query). Heads 8..15: anti-causal (key >= query).
// 256 threads: thread t owns row r=t/4, column quarter q=t%4 (16 cols).
// ---------------------------------------------------------------------------
#define ATTN_SMEM (4 * 64 * 65 * 4)

__global__ void __launch_bounds__(256)
attn_kernel(const float* __restrict__ Q,
            const float* __restrict__ K,
            const float* __restrict__ V,
            float* __restrict__ O) {
    extern __shared__ float sm[];
    float* Qs = sm;                 // 64 x 65
    float* Ks = Qs + 64 * 65;
    float* Vs = Ks + 64 * 65;
    float* Ps = Vs + 64 * 65;

    const int qt  = blockIdx.x;     // 0..31
    const int h   = blockIdx.y;     // 0..15
    const int b   = blockIdx.z;     // 0..1
    const bool causal = (h < 8);
    const int tid = threadIdx.x;
    const int r   = tid >> 2;       // row 0..63
    const int c0  = (tid & 3) << 4; // column base 0,16,32,48

    const long base = (long)(b * NHEAD + h) * NTOK * HDIM;
    const float* Qg = Q + base + (long)qt * 64 * HDIM;

    for (int i = tid; i < 64 * 64; i += 256) {
        int rr = i >> 6, dd = i & 63;
        Qs[rr * 65 + dd] = Qg[i];
    }

    float m_run = -1e30f, l_run = 0.f;
    float o_acc[16];
    #pragma unroll
    for (int j = 0; j < 16; j++) o_acc[j] = 0.f;

    const int gq  = qt * 64 + r;
    const int kt0 = causal ? 0 : qt;
    const int kt1 = causal ? qt : 31;

    for (int kt = kt0; kt <= kt1; kt++) {
        __syncthreads();   // previous iter done reading Ks/Vs/Ps
        const float* Kg = K + base + (long)kt * 64 * HDIM;
        const float* Vg = V + base + (long)kt * 64 * HDIM;
        for (int i = tid; i < 64 * 64; i += 256) {
            int rr = i >> 6, dd = i & 63;
            Ks[rr * 65 + dd] = Kg[i];
            Vs[rr * 65 + dd] = Vg[i];
        }
        __syncthreads();

        // S[r][c0+j] = Q[r] . K[c0+j]
        float s[16];
        #pragma unroll
        for (int j = 0; j < 16; j++) s[j] = 0.f;
        #pragma unroll 8
        for (int d = 0; d < 64; d++) {
            float qv = Qs[r * 65 + d];
            #pragma unroll
            for (int j = 0; j < 16; j++)
                s[j] += qv * Ks[(c0 + j) * 65 + d];
        }

        // scale + mask
        #pragma unroll
        for (int j = 0; j < 16; j++) {
            int gk = kt * 64 + c0 + j;
            bool ok = causal ? (gk <= gq) : (gk >= gq);
            s[j] = ok ? s[j] * 0.125f : -1e30f;
        }

        // row max across 16 local + 4 lanes of the group
        float mt = s[0];
        #pragma unroll
        for (int j = 1; j < 16; j++) mt = fmaxf(mt, s[j]);
        mt = fmaxf(mt, __shfl_xor_sync(0xffffffffu, mt, 1));
        mt = fmaxf(mt, __shfl_xor_sync(0xffffffffu, mt, 2));

        float m_new = fmaxf(m_run, mt);
        float corr  = __expf(m_run - m_new);

        float lsum = 0.f;
        #pragma unroll
        for (int j = 0; j < 16; j++) {
            float p = __expf(s[j] - m_new);
            Ps[r * 65 + c0 + j] = p;
            lsum += p;
        }
        lsum += __shfl_xor_sync(0xffffffffu, lsum, 1);
        lsum += __shfl_xor_sync(0xffffffffu, lsum, 2);

        l_run = l_run * corr + lsum;
        m_run = m_new;
        #pragma unroll
        for (int j = 0; j < 16; j++) o_acc[j] *= corr;

        __syncwarp();   // Ps rows are warp-private: r in [8w, 8w+8)

        #pragma unroll 8
        for (int k = 0; k < 64; k++) {
            float pv = Ps[r * 65 + k];
            #pragma unroll
            for (int j = 0; j < 16; j++)
                o_acc[j] += pv * Vs[k * 65 + c0 + j];
        }
    }

    float inv_l = 1.f / l_run;
    float* Og = O + base + (long)qt * 64 * HDIM;
    #pragma unroll
    for (int j = 0; j < 16; j++)
        Og[r * 64 + c0 + j] = o_acc[j] * inv_l;
}

// ---------------------------------------------------------------------------
extern "C" void kernel_launch(void* const* d_in, const int* in_sizes, int n_in,
                              void* d_out, int out_size) {
    const float* x     = (const float*)d_in[0];
    const float* Wq_lb = (const float*)d_in[1];
    const float* Wk_lb = (const float*)d_in[2];
    const float* Wv_lb = (const float*)d_in[3];
    const float* Wq_la = (const float*)d_in[4];
    const float* Wk_la = (const float*)d_in[5];
    const float* Wv_la = (const float*)d_in[6];
    const float* Wo    = (const float*)d_in[7];

    float *Qp, *Kp, *Vp, *Op;
    cudaGetSymbolAddress((void**)&Qp, g_Q);
    cudaGetSymbolAddress((void**)&Kp, g_K);
    cudaGetSymbolAddress((void**)&Vp, g_V);
    cudaGetSymbolAddress((void**)&Op, g_O);

    dim3 ggrid(DIM / 64, (BSZ * NTOK) / 64);   // (16, 64)
    dim3 gblk(256);

    // QKV projections -> (B,H,N,E)
    sgemm64<true><<<ggrid, gblk>>>(x, Wq_lb, Wq_la, 512, Qp);
    sgemm64<true><<<ggrid, gblk>>>(x, Wk_lb, Wk_la, 512, Kp);
    sgemm64<true><<<ggrid, gblk>>>(x, Wv_lb, Wv_la, 512, Vp);

    // Attention
    cudaFuncSetAttribute(attn_kernel,
                         cudaFuncAttributeMaxDynamicSharedMemorySize, ATTN_SMEM);
    dim3 agrid(NTOK / 64, NHEAD, BSZ);         // (32, 16, 2)
    attn_kernel<<<agrid, 256, ATTN_SMEM>>>(Qp, Kp, Vp, Op);

    // Output projection: flat (B,H,N,E) buffer == reshaped (B*N, D) matrix
    sgemm64<false><<<ggrid, gblk>>>(Op, Wo, Wo, 1024, (float*)d_out);
}

// round 2
// speedup vs baseline: 4.6731x; 4.6731x over previous
#include <cuda_runtime.h>

// Problem constants
#define BSZ   2
#define NTOK  2048          // T*F
#define DIM   1024
#define NHEAD 16
#define HDIM  64

// Scratch: Q,K,V,O in (B, H, N, E) layout.
__device__ float g_Q[BSZ * NHEAD * NTOK * HDIM];
__device__ float g_K[BSZ * NHEAD * NTOK * HDIM];
__device__ float g_V[BSZ * NHEAD * NTOK * HDIM];
__device__ float g_O[BSZ * NHEAD * NTOK * HDIM];

__device__ __forceinline__ unsigned f2tf(float x) {
    unsigned r;
    asm("cvt.rna.tf32.f32 %0, %1;" : "=r"(r) : "f"(x));
    return r;
}

__device__ __forceinline__ void mma_tf32(
    float& c0, float& c1, float& c2, float& c3,
    unsigned a0, unsigned a1, unsigned a2, unsigned a3,
    unsigned b0, unsigned b1)
{
    asm volatile(
        "mma.sync.aligned.m16n8k8.row.col.f32.tf32.tf32.f32 "
        "{%0,%1,%2,%3}, {%4,%5,%6,%7}, {%8,%9}, {%0,%1,%2,%3};"
        : "+f"(c0), "+f"(c1), "+f"(c2), "+f"(c3)
        : "r"(a0), "r"(a1), "r"(a2), "r"(a3), "r"(b0), "r"(b1));
}

// ---------------------------------------------------------------------------
// tf32 mma GEMM: C[4096,1024] = A[4096,1024] * W^T,
// W row j from Wlb[j] if j<split else Wla[j-split] (both K-major, col-major B).
// Block tile 128x128, BK=16, 8 warps of 64x32.
// ---------------------------------------------------------------------------
#define GSTRIDE 136   // smem row stride (words): 136%32==8 -> conflict-free frags

template <bool SCATTER>
__global__ void __launch_bounds__(256, 2)
mma_gemm(const float* __restrict__ A,
         const float* __restrict__ Wlb,
         const float* __restrict__ Wla,
         int split,
         float* __restrict__ Cout) {
    __shared__ unsigned As[16 * GSTRIDE];
    __shared__ unsigned Bs[16 * GSTRIDE];

    const int tid  = threadIdx.x;
    const int lane = tid & 31;
    const int wid  = tid >> 5;
    const int wm   = (wid >> 2) * 64;   // warp m offset in tile
    const int wn   = (wid & 3) * 32;    // warp n offset in tile
    const int row0 = blockIdx.y * 128;
    const int col0 = blockIdx.x * 128;

    float acc[4][4][4] = {};

    for (int kt = 0; kt < DIM / 16; kt++) {
        const int k0 = kt * 16;
        __syncthreads();
        // Load A/B tiles (128 rows x 16 k) as tf32 into [k][m] layout.
        // id = kc*128 + m  -> conflict-free STS.
        #pragma unroll
        for (int i = 0; i < 2; i++) {
            int id = tid + i * 256;
            int m  = id & 127;
            int kc = id >> 7;
            float4 v = *reinterpret_cast<const float4*>(
                &A[(size_t)(row0 + m) * DIM + k0 + kc * 4]);
            As[(kc * 4 + 0) * GSTRIDE + m] = f2tf(v.x);
            As[(kc * 4 + 1) * GSTRIDE + m] = f2tf(v.y);
            As[(kc * 4 + 2) * GSTRIDE + m] = f2tf(v.z);
            As[(kc * 4 + 3) * GSTRIDE + m] = f2tf(v.w);

            int j = col0 + m;
            const float* W = (j < split) ? Wlb : Wla;
            int jj = (j < split) ? j : (j - split);
            float4 u = *reinterpret_cast<const float4*>(
                &W[(size_t)jj * DIM + k0 + kc * 4]);
            Bs[(kc * 4 + 0) * GSTRIDE + m] = f2tf(u.x);
            Bs[(kc * 4 + 1) * GSTRIDE + m] = f2tf(u.y);
            Bs[(kc * 4 + 2) * GSTRIDE + m] = f2tf(u.z);
            Bs[(kc * 4 + 3) * GSTRIDE + m] = f2tf(u.w);
        }
        __syncthreads();

        #pragma unroll
        for (int ks = 0; ks < 2; ks++) {
            const int kk = ks * 8 + (lane & 3);
            unsigned a[4][4], b[4][2];
            #pragma unroll
            for (int mi = 0; mi < 4; mi++) {
                int mb = wm + mi * 16 + (lane >> 2);
                a[mi][0] = As[kk * GSTRIDE + mb];
                a[mi][1] = As[kk * GSTRIDE + mb + 8];
                a[mi][2] = As[(kk + 4) * GSTRIDE + mb];
                a[mi][3] = As[(kk + 4) * GSTRIDE + mb + 8];
            }
            #pragma unroll
            for (int ni = 0; ni < 4; ni++) {
                int nb = wn + ni * 8 + (lane >> 2);
                b[ni][0] = Bs[kk * GSTRIDE + nb];
                b[ni][1] = Bs[(kk + 4) * GSTRIDE + nb];
            }
            #pragma unroll
            for (int mi = 0; mi < 4; mi++)
                #pragma unroll
                for (int ni = 0; ni < 4; ni++)
                    mma_tf32(acc[mi][ni][0], acc[mi][ni][1],
                             acc[mi][ni][2], acc[mi][ni][3],
                             a[mi][0], a[mi][1], a[mi][2], a[mi][3],
                             b[ni][0], b[ni][1]);
        }
    }

    // Epilogue
    #pragma unroll
    for (int mi = 0; mi < 4; mi++) {
        int r = row0 + wm + mi * 16 + (lane >> 2);
        #pragma unroll
        for (int ni = 0; ni < 4; ni++) {
            int c = col0 + wn + ni * 8 + 2 * (lane & 3);
            if (SCATTER) {
                int b = r >> 11, n = r & 2047;
                int h = c >> 6,  e = c & 63;
                float2 v0 = make_float2(acc[mi][ni][0], acc[mi][ni][1]);
                float2 v1 = make_float2(acc[mi][ni][2], acc[mi][ni][3]);
                *reinterpret_cast<float2*>(
                    &Cout[(((size_t)(b * NHEAD + h) * NTOK + n) * HDIM) + e]) = v0;
                *reinterpret_cast<float2*>(
                    &Cout[(((size_t)(b * NHEAD + h) * NTOK + n + 8) * HDIM) + e]) = v1;
            } else {
                float2 v0 = make_float2(acc[mi][ni][0], acc[mi][ni][1]);
                float2 v1 = make_float2(acc[mi][ni][2], acc[mi][ni][3]);
                *reinterpret_cast<float2*>(&Cout[(size_t)r * DIM + c]) = v0;
                *reinterpret_cast<float2*>(&Cout[(size_t)(r + 8) * DIM + c]) = v1;
            }
        }
    }
}

// ---------------------------------------------------------------------------
// Flash attention with tf32 mma. Block = (qtile 64, head, batch), 4 warps.
// Warp w owns query rows [w*16, w*16+16). Heads 0..7 causal, 8..15 anti.
// S = Q K^T via mma; softmax on C-frags; P->A-frags via shuffles; PV via mma.
// ---------------------------------------------------------------------------
#define KSTRIDE 72    // 72%32==8 -> conflict-free fragment LDS

__global__ void __launch_bounds__(128)
attn_mma(const float* __restrict__ Q,
         const float* __restrict__ K,
         const float* __restrict__ V,
         float* __restrict__ O) {
    __shared__ unsigned Ks[64 * KSTRIDE];   // [e][key]
    __shared__ unsigned Vs[64 * KSTRIDE];   // [key][e]

    const int qt  = blockIdx.x;
    const int h   = blockIdx.y;
    const int b   = blockIdx.z;
    const bool causal = (h < 8);
    const int tid  = threadIdx.x;
    const int lane = tid & 31;
    const int w    = tid >> 5;
    const int quad = lane & 3;
    const int gpr  = lane >> 2;   // group row 0..7

    const size_t base = (size_t)(b * NHEAD + h) * NTOK * HDIM;
    const float* Qg = Q + base;
    const float* Kg = K + base;
    const float* Vg = V + base;

    // Preload Q fragments (16 rows x 64 k) for this warp.
    const int qrow0 = qt * 64 + w * 16;
    unsigned qa[8][4];
    #pragma unroll
    for (int ks = 0; ks < 8; ks++) {
        int kk = ks * 8 + quad;
        qa[ks][0] = f2tf(Qg[(size_t)(qrow0 + gpr) * HDIM + kk]);
        qa[ks][1] = f2tf(Qg[(size_t)(qrow0 + gpr + 8) * HDIM + kk]);
        qa[ks][2] = f2tf(Qg[(size_t)(qrow0 + gpr) * HDIM + kk + 4]);
        qa[ks][3] = f2tf(Qg[(size_t)(qrow0 + gpr + 8) * HDIM + kk + 4]);
    }

    float o[8][4];
    #pragma unroll
    for (int ni = 0; ni < 8; ni++)
        #pragma unroll
        for (int j = 0; j < 4; j++) o[ni][j] = 0.f;

    float m0 = -1e30f, m1 = -1e30f, l0 = 0.f, l1 = 0.f;
    const int gq0 = qrow0 + gpr;
    const int gq1 = gq0 + 8;

    const int kt0 = causal ? 0 : qt;
    const int kt1 = causal ? qt : (NTOK / 64 - 1);

    for (int kt = kt0; kt <= kt1; kt++) {
        __syncthreads();
        // Load K tile transposed -> Ks[e][key]; V tile -> Vs[key][e] (tf32).
        #pragma unroll
        for (int i = 0; i < 8; i++) {
            int id = tid + i * 128;
            {   // K: id = ec*64 + key
                int key = id & 63, ec = id >> 6;
                float4 v = *reinterpret_cast<const float4*>(
                    &Kg[(size_t)(kt * 64 + key) * HDIM + ec * 4]);
                Ks[(ec * 4 + 0) * KSTRIDE + key] = f2tf(v.x);
                Ks[(ec * 4 + 1) * KSTRIDE + key] = f2tf(v.y);
                Ks[(ec * 4 + 2) * KSTRIDE + key] = f2tf(v.z);
                Ks[(ec * 4 + 3) * KSTRIDE + key] = f2tf(v.w);
            }
            {   // V: id = key*16 + ec
                int key = id >> 4, ec = id & 15;
                float4 v = *reinterpret_cast<const float4*>(
                    &Vg[(size_t)(kt * 64 + key) * HDIM + ec * 4]);
                uint4 u;
                u.x = f2tf(v.x); u.y = f2tf(v.y);
                u.z = f2tf(v.z); u.w = f2tf(v.w);
                *reinterpret_cast<uint4*>(&Vs[key * KSTRIDE + ec * 4]) = u;
            }
        }
        __syncthreads();

        // S = Q K^T  (16 x 64 per warp)
        float sc[8][4];
        #pragma unroll
        for (int ni = 0; ni < 8; ni++)
            #pragma unroll
            for (int j = 0; j < 4; j++) sc[ni][j] = 0.f;

        #pragma unroll
        for (int ks = 0; ks < 8; ks++) {
            const int kk = ks * 8 + quad;
            #pragma unroll
            for (int ni = 0; ni < 8; ni++) {
                unsigned b0 = Ks[kk * KSTRIDE + ni * 8 + gpr];
                unsigned b1 = Ks[(kk + 4) * KSTRIDE + ni * 8 + gpr];
                mma_tf32(sc[ni][0], sc[ni][1], sc[ni][2], sc[ni][3],
                         qa[ks][0], qa[ks][1], qa[ks][2], qa[ks][3], b0, b1);
            }
        }

        // scale + mask
        const bool diag = (kt == qt);
        #pragma unroll
        for (int ni = 0; ni < 8; ni++) {
            int gk = kt * 64 + ni * 8 + 2 * quad;
            #pragma unroll
            for (int j = 0; j < 4; j++) sc[ni][j] *= 0.125f;
            if (diag) {
                bool k0r0 = causal ? (gk     <= gq0) : (gk     >= gq0);
                bool k1r0 = causal ? (gk + 1 <= gq0) : (gk + 1 >= gq0);
                bool k0r1 = causal ? (gk     <= gq1) : (gk     >= gq1);
                bool k1r1 = causal ? (gk + 1 <= gq1) : (gk + 1 >= gq1);
                if (!k0r0) sc[ni][0] = -1e30f;
                if (!k1r0) sc[ni][1] = -1e30f;
                if (!k0r1) sc[ni][2] = -1e30f;
                if (!k1r1) sc[ni][3] = -1e30f;
            }
        }

        // row max (16 vals per row per thread, then across quad)
        float mt0 = -1e30f, mt1 = -1e30f;
        #pragma unroll
        for (int ni = 0; ni < 8; ni++) {
            mt0 = fmaxf(mt0, fmaxf(sc[ni][0], sc[ni][1]));
            mt1 = fmaxf(mt1, fmaxf(sc[ni][2], sc[ni][3]));
        }
        mt0 = fmaxf(mt0, __shfl_xor_sync(0xffffffffu, mt0, 1));
        mt0 = fmaxf(mt0, __shfl_xor_sync(0xffffffffu, mt0, 2));
        mt1 = fmaxf(mt1, __shfl_xor_sync(0xffffffffu, mt1, 1));
        mt1 = fmaxf(mt1, __shfl_xor_sync(0xffffffffu, mt1, 2));

        float mn0 = fmaxf(m0, mt0), mn1 = fmaxf(m1, mt1);
        float cr0 = __expf(m0 - mn0), cr1 = __expf(m1 - mn1);
        m0 = mn0; m1 = mn1;

        // exponentiate -> P (tf32 bits), row sums
        unsigned pt[8][4];
        float ls0 = 0.f, ls1 = 0.f;
        #pragma unroll
        for (int ni = 0; ni < 8; ni++) {
            float p0 = __expf(sc[ni][0] - mn0);
            float p1 = __expf(sc[ni][1] - mn0);
            float p2 = __expf(sc[ni][2] - mn1);
            float p3 = __expf(sc[ni][3] - mn1);
            ls0 += p0 + p1; ls1 += p2 + p3;
            pt[ni][0] = f2tf(p0); pt[ni][1] = f2tf(p1);
            pt[ni][2] = f2tf(p2); pt[ni][3] = f2tf(p3);
        }
        ls0 += __shfl_xor_sync(0xffffffffu, ls0, 1);
        ls0 += __shfl_xor_sync(0xffffffffu, ls0, 2);
        ls1 += __shfl_xor_sync(0xffffffffu, ls1, 1);
        ls1 += __shfl_xor_sync(0xffffffffu, ls1, 2);
        l0 = l0 * cr0 + ls0;
        l1 = l1 * cr1 + ls1;

        #pragma unroll
        for (int ni = 0; ni < 8; ni++) {
            o[ni][0] *= cr0; o[ni][1] *= cr0;
            o[ni][2] *= cr1; o[ni][3] *= cr1;
        }

        // PV: convert P C-frags -> A-frags via shuffles, mma against V.
        const int src  = (lane & ~3) | (quad >> 1);
        const int src2 = src + 2;
        const bool odd = (lane & 1);
        #pragma unroll
        for (int ks = 0; ks < 8; ks++) {
            unsigned v0 = __shfl_sync(0xffffffffu, pt[ks][0], src);
            unsigned v1 = __shfl_sync(0xffffffffu, pt[ks][1], src);
            unsigned v2 = __shfl_sync(0xffffffffu, pt[ks][2], src);
            unsigned v3 = __shfl_sync(0xffffffffu, pt[ks][3], src);
            unsigned w0 = __shfl_sync(0xffffffffu, pt[ks][0], src2);
            unsigned w1 = __shfl_sync(0xffffffffu, pt[ks][1], src2);
            unsigned w2 = __shfl_sync(0xffffffffu, pt[ks][2], src2);
            unsigned w3 = __shfl_sync(0xffffffffu, pt[ks][3], src2);
            unsigned pa0 = odd ? v1 : v0;
            unsigned pa1 = odd ? v3 : v2;
            unsigned pa2 = odd ? w1 : w0;
            unsigned pa3 = odd ? w3 : w2;
            const int kk = ks * 8 + quad;
            #pragma unroll
            for (int ni = 0; ni < 8; ni++) {
                unsigned b0 = Vs[kk * KSTRIDE + ni * 8 + gpr];
                unsigned b1 = Vs[(kk + 4) * KSTRIDE + ni * 8 + gpr];
                mma_tf32(o[ni][0], o[ni][1], o[ni][2], o[ni][3],
                         pa0, pa1, pa2, pa3, b0, b1);
            }
        }
    }

    // write O
    float inv0 = 1.f / l0, inv1 = 1.f / l1;
    float* Og = O + base;
    #pragma unroll
    for (int ni = 0; ni < 8; ni++) {
        int c = ni * 8 + 2 * quad;
        float2 r0 = make_float2(o[ni][0] * inv0, o[ni][1] * inv0);
        float2 r1 = make_float2(o[ni][2] * inv1, o[ni][3] * inv1);
        *reinterpret_cast<float2*>(&Og[(size_t)gq0 * HDIM + c]) = r0;
        *reinterpret_cast<float2*>(&Og[(size_t)gq1 * HDIM + c]) = r1;
    }
}

// ---------------------------------------------------------------------------
extern "C" void kernel_launch(void* const* d_in, const int* in_sizes, int n_in,
                              void* d_out, int out_size) {
    const float* x     = (const float*)d_in[0];
    const float* Wq_lb = (const float*)d_in[1];
    const float* Wk_lb = (const float*)d_in[2];
    const float* Wv_lb = (const float*)d_in[3];
    const float* Wq_la = (const float*)d_in[4];
    const float* Wk_la = (const float*)d_in[5];
    const float* Wv_la = (const float*)d_in[6];
    const float* Wo    = (const float*)d_in[7];

    float *Qp, *Kp, *Vp, *Op;
    cudaGetSymbolAddress((void**)&Qp, g_Q);
    cudaGetSymbolAddress((void**)&Kp, g_K);
    cudaGetSymbolAddress((void**)&Vp, g_V);
    cudaGetSymbolAddress((void**)&Op, g_O);

    dim3 ggrid(DIM / 128, (BSZ * NTOK) / 128);   // (8, 32)

    mma_gemm<true><<<ggrid, 256>>>(x, Wq_lb, Wq_la, 512, Qp);
    mma_gemm<true><<<ggrid, 256>>>(x, Wk_lb, Wk_la, 512, Kp);
    mma_gemm<true><<<ggrid, 256>>>(x, Wv_lb, Wv_la, 512, Vp);

    dim3 agrid(NTOK / 64, NHEAD, BSZ);           // (32, 16, 2)
    attn_mma<<<agrid, 128>>>(Qp, Kp, Vp, Op);

    mma_gemm<false><<<ggrid, 256>>>(Op, Wo, Wo, 1024, (float*)d_out);
}

// round 3
// speedup vs baseline: 6.1206x; 1.3098x over previous
#include <cuda_runtime.h>
#include <cuda_fp16.h>

#define BSZ   2
#define NTOK  2048
#define DIM   1024
#define NHEAD 16
#define HDIM  64

// QKV scratch: 3 matrices x (B, 16, N, E); O scratch (B, 16, N, E) flat.
__device__ float g_QKV[3 * BSZ * NHEAD * NTOK * HDIM];
__device__ float g_O[BSZ * NHEAD * NTOK * HDIM];

// ---------------- primitives -------------------------------------------------
__device__ __forceinline__ void split2(float x, float y, unsigned& h, unsigned& l) {
    __half2 hh = __floats2half2_rn(x, y);
    float2 hf = __half22float2(hh);
    __half2 ll = __floats2half2_rn(x - hf.x, y - hf.y);
    h = *reinterpret_cast<unsigned*>(&hh);
    l = *reinterpret_cast<unsigned*>(&ll);
}

__device__ __forceinline__ void mma16(float* c,
                                      const unsigned* a,
                                      unsigned b0, unsigned b1) {
    asm volatile(
        "mma.sync.aligned.m16n8k16.row.col.f32.f16.f16.f32 "
        "{%0,%1,%2,%3}, {%4,%5,%6,%7}, {%8,%9}, {%0,%1,%2,%3};"
        : "+f"(c[0]), "+f"(c[1]), "+f"(c[2]), "+f"(c[3])
        : "r"(a[0]), "r"(a[1]), "r"(a[2]), "r"(a[3]), "r"(b0), "r"(b1));
}

__device__ __forceinline__ void ldsm4(unsigned* r, unsigned addr) {
    asm volatile("ldmatrix.sync.aligned.m8n8.x4.shared.b16 {%0,%1,%2,%3}, [%4];"
        : "=r"(r[0]), "=r"(r[1]), "=r"(r[2]), "=r"(r[3]) : "r"(addr));
}
__device__ __forceinline__ void ldsm2(unsigned& r0, unsigned& r1, unsigned addr) {
    asm volatile("ldmatrix.sync.aligned.m8n8.x2.shared.b16 {%0,%1}, [%2];"
        : "=r"(r0), "=r"(r1) : "r"(addr));
}
__device__ __forceinline__ void ldsm2t(unsigned& r0, unsigned& r1, unsigned addr) {
    asm volatile("ldmatrix.sync.aligned.m8n8.x2.trans.shared.b16 {%0,%1}, [%2];"
        : "=r"(r0), "=r"(r1) : "r"(addr));
}

// ---------------------------------------------------------------------------
// fp16x3 GEMM: C[4096, N] = A[4096,1024] * W^T
// MODE 0: fused QKV (N=3072), weight from 6 stacked tensors, scatter epilogue.
// MODE 1: output projection (N=1024), W0 row-major, plain epilogue.
// Tile 128x128xBK32, 8 warps (64x32 each), smem tiles as fp16 hi/lo.
// ---------------------------------------------------------------------------
#define GSTR 40   // fp16 row stride (elems): 80B = 5 chunks -> LDSM conflict-free

template <int MODE>
__global__ void __launch_bounds__(256)
gemm_f16x3(const float* __restrict__ A,
           const float* __restrict__ W0, const float* __restrict__ W1,
           const float* __restrict__ W2, const float* __restrict__ W3,
           const float* __restrict__ W4, const float* __restrict__ W5,
           float* __restrict__ Cout) {
    __shared__ unsigned sAh[128 * 20], sAl[128 * 20];
    __shared__ unsigned sBh[128 * 20], sBl[128 * 20];

    const int tid  = threadIdx.x;
    const int lane = tid & 31;
    const int wid  = tid >> 5;
    const int wm   = (wid >> 2) * 64;
    const int wn   = (wid & 3) * 32;
    const int row0 = blockIdx.y * 128;
    const int col0 = blockIdx.x * 128;

    // weight pointer for this column tile (tile never crosses a 512 boundary)
    const float* W;
    int wr0;
    if (MODE == 0) {
        int m  = col0 >> 10;
        int j0 = col0 & 1023;
        const float* Wt0 = (m == 0) ? W0 : (m == 1) ? W2 : W4;
        const float* Wt1 = (m == 0) ? W1 : (m == 1) ? W3 : W5;
        W   = (j0 < 512) ? Wt0 : Wt1;
        wr0 = j0 & 511;
    } else {
        W   = W0;
        wr0 = col0;
    }

    const unsigned aAh = (unsigned)__cvta_generic_to_shared(sAh);
    const unsigned aAl = (unsigned)__cvta_generic_to_shared(sAl);
    const unsigned aBh = (unsigned)__cvta_generic_to_shared(sBh);
    const unsigned aBl = (unsigned)__cvta_generic_to_shared(sBl);

    float acc[4][4][4] = {};
    float4 ra[4], rb[4];

    // prefetch stage 0
    #pragma unroll
    for (int i = 0; i < 4; i++) {
        int id = tid + i * 256;
        int rw = id >> 3, kc = id & 7;
        ra[i] = *reinterpret_cast<const float4*>(&A[(size_t)(row0 + rw) * DIM + kc * 4]);
        rb[i] = *reinterpret_cast<const float4*>(&W[(size_t)(wr0 + rw) * DIM + kc * 4]);
    }

    for (int s = 0; s < 32; s++) {
        // store staged regs -> smem (split hi/lo)
        #pragma unroll
        for (int i = 0; i < 4; i++) {
            int id = tid + i * 256;
            int rw = id >> 3, kc = id & 7;
            unsigned h0, h1, l0, l1;
            split2(ra[i].x, ra[i].y, h0, l0);
            split2(ra[i].z, ra[i].w, h1, l1);
            *reinterpret_cast<uint2*>(&sAh[rw * 20 + kc * 2]) = make_uint2(h0, h1);
            *reinterpret_cast<uint2*>(&sAl[rw * 20 + kc * 2]) = make_uint2(l0, l1);
            split2(rb[i].x, rb[i].y, h0, l0);
            split2(rb[i].z, rb[i].w, h1, l1);
            *reinterpret_cast<uint2*>(&sBh[rw * 20 + kc * 2]) = make_uint2(h0, h1);
            *reinterpret_cast<uint2*>(&sBl[rw * 20 + kc * 2]) = make_uint2(l0, l1);
        }
        __syncthreads();

        // prefetch next stage
        if (s + 1 < 32) {
            int k0 = (s + 1) * 32;
            #pragma unroll
            for (int i = 0; i < 4; i++) {
                int id = tid + i * 256;
                int rw = id >> 3, kc = id & 7;
                ra[i] = *reinterpret_cast<const float4*>(
                    &A[(size_t)(row0 + rw) * DIM + k0 + kc * 4]);
                rb[i] = *reinterpret_cast<const float4*>(
                    &W[(size_t)(wr0 + rw) * DIM + k0 + kc * 4]);
            }
        }

        // MMA over the stage
        #pragma unroll
        for (int ks = 0; ks < 2; ks++) {
            unsigned ah[4][4], al[4][4], bh[4][2], bl[4][2];
            #pragma unroll
            for (int mi = 0; mi < 4; mi++) {
                unsigned off = ((wm + mi * 16 + (lane & 15)) * GSTR
                                + ks * 16 + (lane >> 4) * 8) * 2;
                ldsm4(ah[mi], aAh + off);
                ldsm4(al[mi], aAl + off);
            }
            #pragma unroll
            for (int ni = 0; ni < 4; ni++) {
                unsigned off = ((wn + ni * 8 + (lane & 7)) * GSTR
                                + ks * 16 + ((lane >> 3) & 1) * 8) * 2;
                ldsm2(bh[ni][0], bh[ni][1], aBh + off);
                ldsm2(bl[ni][0], bl[ni][1], aBl + off);
            }
            #pragma unroll
            for (int mi = 0; mi < 4; mi++)
                #pragma unroll
                for (int ni = 0; ni < 4; ni++) {
                    mma16(acc[mi][ni], ah[mi], bh[ni][0], bh[ni][1]);
                    mma16(acc[mi][ni], al[mi], bh[ni][0], bh[ni][1]);
                    mma16(acc[mi][ni], ah[mi], bl[ni][0], bl[ni][1]);
                }
        }
        __syncthreads();
    }

    // epilogue
    #pragma unroll
    for (int mi = 0; mi < 4; mi++) {
        int r = row0 + wm + mi * 16 + (lane >> 2);
        #pragma unroll
        for (int ni = 0; ni < 4; ni++) {
            int c = col0 + wn + ni * 8 + 2 * (lane & 3);
            float2 v0 = make_float2(acc[mi][ni][0], acc[mi][ni][1]);
            float2 v1 = make_float2(acc[mi][ni][2], acc[mi][ni][3]);
            if (MODE == 0) {
                int m = c >> 10, j = c & 1023;
                int h = j >> 6,  e = j & 63;
                int b = r >> 11, n = r & 2047;
                size_t idx = ((((size_t)(m * 2 + b) * 16 + h) * NTOK) + n) * HDIM + e;
                *reinterpret_cast<float2*>(&Cout[idx])             = v0;
                *reinterpret_cast<float2*>(&Cout[idx + 8 * HDIM])  = v1;
            } else {
                *reinterpret_cast<float2*>(&Cout[(size_t)r * DIM + c])       = v0;
                *reinterpret_cast<float2*>(&Cout[(size_t)(r + 8) * DIM + c]) = v1;
            }
        }
    }
}

// ---------------------------------------------------------------------------
// fp16x3 flash attention. Block = (qtile 64, head, batch), 4 warps.
// Warp w: query rows [w*16, w*16+16). Heads 0..7 causal, 8..15 anti-causal.
// ---------------------------------------------------------------------------
#define KSTR 72   // fp16 row stride: 144B = 9 chunks -> LDSM conflict-free

__global__ void __launch_bounds__(128)
attn_f16x3(const float* __restrict__ QKV, float* __restrict__ O) {
    __shared__ unsigned sKh[64 * 36], sKl[64 * 36];   // [key][e]
    __shared__ unsigned sVh[64 * 36], sVl[64 * 36];   // [key][e]

    const int qt  = blockIdx.x;
    const int h   = blockIdx.y;
    const int b   = blockIdx.z;
    const bool causal = (h < 8);
    const int tid  = threadIdx.x;
    const int lane = tid & 31;
    const int w    = tid >> 5;
    const int quad = lane & 3;
    const int gpr  = lane >> 2;

    const float* Qg = QKV + ((size_t)(0 + b) * 16 + h) * NTOK * HDIM;
    const float* Kg = QKV + ((size_t)(2 + b) * 16 + h) * NTOK * HDIM;
    const float* Vg = QKV + ((size_t)(4 + b) * 16 + h) * NTOK * HDIM;

    const unsigned aKh = (unsigned)__cvta_generic_to_shared(sKh);
    const unsigned aKl = (unsigned)__cvta_generic_to_shared(sKl);
    const unsigned aVh = (unsigned)__cvta_generic_to_shared(sVh);
    const unsigned aVl = (unsigned)__cvta_generic_to_shared(sVl);

    // preload + split Q fragments (16 rows x 64 e)
    const int qrow0 = qt * 64 + w * 16;
    const int gq0 = qrow0 + gpr;
    const int gq1 = gq0 + 8;
    unsigned qh[4][4], ql[4][4];
    #pragma unroll
    for (int ks = 0; ks < 4; ks++) {
        float2 v00 = *reinterpret_cast<const float2*>(&Qg[(size_t)gq0 * HDIM + ks * 16 + 2 * quad]);
        float2 v10 = *reinterpret_cast<const float2*>(&Qg[(size_t)gq1 * HDIM + ks * 16 + 2 * quad]);
        float2 v01 = *reinterpret_cast<const float2*>(&Qg[(size_t)gq0 * HDIM + ks * 16 + 8 + 2 * quad]);
        float2 v11 = *reinterpret_cast<const float2*>(&Qg[(size_t)gq1 * HDIM + ks * 16 + 8 + 2 * quad]);
        split2(v00.x, v00.y, qh[ks][0], ql[ks][0]);
        split2(v10.x, v10.y, qh[ks][1], ql[ks][1]);
        split2(v01.x, v01.y, qh[ks][2], ql[ks][2]);
        split2(v11.x, v11.y, qh[ks][3], ql[ks][3]);
    }

    float o[8][4] = {};
    float m0 = -1e30f, m1 = -1e30f, l0 = 0.f, l1 = 0.f;

    const int kt0 = causal ? 0 : qt;
    const int kt1 = causal ? qt : (NTOK / 64 - 1);

    for (int kt = kt0; kt <= kt1; kt++) {
        __syncthreads();
        // load + split K,V tiles (64x64 each)
        #pragma unroll
        for (int i = 0; i < 8; i++) {
            int id  = tid + i * 128;             // 0..1023 float4 slots
            int key = id >> 4, ec = id & 15;
            unsigned h0, h1, l0r, l1r;
            float4 kv = *reinterpret_cast<const float4*>(
                &Kg[(size_t)(kt * 64 + key) * HDIM + ec * 4]);
            split2(kv.x, kv.y, h0, l0r);
            split2(kv.z, kv.w, h1, l1r);
            *reinterpret_cast<uint2*>(&sKh[key * 36 + ec * 2]) = make_uint2(h0, h1);
            *reinterpret_cast<uint2*>(&sKl[key * 36 + ec * 2]) = make_uint2(l0r, l1r);
            float4 vv = *reinterpret_cast<const float4*>(
                &Vg[(size_t)(kt * 64 + key) * HDIM + ec * 4]);
            split2(vv.x, vv.y, h0, l0r);
            split2(vv.z, vv.w, h1, l1r);
            *reinterpret_cast<uint2*>(&sVh[key * 36 + ec * 2]) = make_uint2(h0, h1);
            *reinterpret_cast<uint2*>(&sVl[key * 36 + ec * 2]) = make_uint2(l0r, l1r);
        }
        __syncthreads();

        // S = Q K^T : n = key blocks (8), k = e slices (4)
        float sc[8][4] = {};
        #pragma unroll
        for (int ks = 0; ks < 4; ks++) {
            #pragma unroll
            for (int ni = 0; ni < 8; ni++) {
                unsigned off = ((ni * 8 + (lane & 7)) * KSTR
                                + ks * 16 + ((lane >> 3) & 1) * 8) * 2;
                unsigned bh0, bh1, bl0, bl1;
                ldsm2(bh0, bh1, aKh + off);
                ldsm2(bl0, bl1, aKl + off);
                mma16(sc[ni], qh[ks], bh0, bh1);
                mma16(sc[ni], ql[ks], bh0, bh1);
                mma16(sc[ni], qh[ks], bl0, bl1);
            }
        }

        // scale + mask
        const bool diag = (kt == qt);
        #pragma unroll
        for (int ni = 0; ni < 8; ni++) {
            #pragma unroll
            for (int j = 0; j < 4; j++) sc[ni][j] *= 0.125f;
            if (diag) {
                int gk = kt * 64 + ni * 8 + 2 * quad;
                if (!(causal ? (gk     <= gq0) : (gk     >= gq0))) sc[ni][0] = -1e30f;
                if (!(causal ? (gk + 1 <= gq0) : (gk + 1 >= gq0))) sc[ni][1] = -1e30f;
                if (!(causal ? (gk     <= gq1) : (gk     >= gq1))) sc[ni][2] = -1e30f;
                if (!(causal ? (gk + 1 <= gq1) : (gk + 1 >= gq1))) sc[ni][3] = -1e30f;
            }
        }

        // online softmax
        float mt0 = -1e30f, mt1 = -1e30f;
        #pragma unroll
        for (int ni = 0; ni < 8; ni++) {
            mt0 = fmaxf(mt0, fmaxf(sc[ni][0], sc[ni][1]));
            mt1 = fmaxf(mt1, fmaxf(sc[ni][2], sc[ni][3]));
        }
        mt0 = fmaxf(mt0, __shfl_xor_sync(0xffffffffu, mt0, 1));
        mt0 = fmaxf(mt0, __shfl_xor_sync(0xffffffffu, mt0, 2));
        mt1 = fmaxf(mt1, __shfl_xor_sync(0xffffffffu, mt1, 1));
        mt1 = fmaxf(mt1, __shfl_xor_sync(0xffffffffu, mt1, 2));

        float mn0 = fmaxf(m0, mt0), mn1 = fmaxf(m1, mt1);
        float cr0 = __expf(m0 - mn0), cr1 = __expf(m1 - mn1);
        m0 = mn0; m1 = mn1;

        float ls0 = 0.f, ls1 = 0.f;
        #pragma unroll
        for (int ni = 0; ni < 8; ni++) {
            sc[ni][0] = __expf(sc[ni][0] - mn0);
            sc[ni][1] = __expf(sc[ni][1] - mn0);
            sc[ni][2] = __expf(sc[ni][2] - mn1);
            sc[ni][3] = __expf(sc[ni][3] - mn1);
            ls0 += sc[ni][0] + sc[ni][1];
            ls1 += sc[ni][2] + sc[ni][3];
        }
        ls0 += __shfl_xor_sync(0xffffffffu, ls0, 1);
        ls0 += __shfl_xor_sync(0xffffffffu, ls0, 2);
        ls1 += __shfl_xor_sync(0xffffffffu, ls1, 1);
        ls1 += __shfl_xor_sync(0xffffffffu, ls1, 2);
        l0 = l0 * cr0 + ls0;
        l1 = l1 * cr1 + ls1;

        #pragma unroll
        for (int ni = 0; ni < 8; ni++) {
            o[ni][0] *= cr0; o[ni][1] *= cr0;
            o[ni][2] *= cr1; o[ni][3] *= cr1;
        }

        // PV: P C-frags are A-frags directly (identity map). n = e blocks.
        #pragma unroll
        for (int ks = 0; ks < 4; ks++) {
            unsigned ph[4], pl[4];
            split2(sc[2 * ks][0],     sc[2 * ks][1],     ph[0], pl[0]);
            split2(sc[2 * ks][2],     sc[2 * ks][3],     ph[1], pl[1]);
            split2(sc[2 * ks + 1][0], sc[2 * ks + 1][1], ph[2], pl[2]);
            split2(sc[2 * ks + 1][2], sc[2 * ks + 1][3], ph[3], pl[3]);
            unsigned vrow = ks * 16 + (lane & 15);
            #pragma unroll
            for (int ni = 0; ni < 8; ni++) {
                unsigned off = (vrow * KSTR + ni * 8) * 2;
                unsigned vh0, vh1, vl0, vl1;
                ldsm2t(vh0, vh1, aVh + off);
                ldsm2t(vl0, vl1, aVl + off);
                mma16(o[ni], ph, vh0, vh1);
                mma16(o[ni], pl, vh0, vh1);
                mma16(o[ni], ph, vl0, vl1);
            }
        }
    }

    // write O (B,H,N,E) flat
    float inv0 = 1.f / l0, inv1 = 1.f / l1;
    float* Og = O + ((size_t)(b * 16 + h)) * NTOK * HDIM;
    #pragma unroll
    for (int ni = 0; ni < 8; ni++) {
        int c = ni * 8 + 2 * quad;
        float2 r0 = make_float2(o[ni][0] * inv0, o[ni][1] * inv0);
        float2 r1 = make_float2(o[ni][2] * inv1, o[ni][3] * inv1);
        *reinterpret_cast<float2*>(&Og[(size_t)gq0 * HDIM + c]) = r0;
        *reinterpret_cast<float2*>(&Og[(size_t)gq1 * HDIM + c]) = r1;
    }
}

// ---------------------------------------------------------------------------
extern "C" void kernel_launch(void* const* d_in, const int* in_sizes, int n_in,
                              void* d_out, int out_size) {
    const float* x     = (const float*)d_in[0];
    const float* Wq_lb = (const float*)d_in[1];
    const float* Wk_lb = (const float*)d_in[2];
    const float* Wv_lb = (const float*)d_in[3];
    const float* Wq_la = (const float*)d_in[4];
    const float* Wk_la = (const float*)d_in[5];
    const float* Wv_la = (const float*)d_in[6];
    const float* Wo    = (const float*)d_in[7];

    float *QKVp, *Op;
    cudaGetSymbolAddress((void**)&QKVp, g_QKV);
    cudaGetSymbolAddress((void**)&Op, g_O);

    // fused QKV projection: N = 3072
    gemm_f16x3<0><<<dim3(24, 32), 256>>>(x, Wq_lb, Wq_la, Wk_lb, Wk_la,
                                         Wv_lb, Wv_la, QKVp);
    // attention
    attn_f16x3<<<dim3(NTOK / 64, NHEAD, BSZ), 128>>>(QKVp, Op);
    // output projection
    gemm_f16x3<1><<<dim3(8, 32), 256>>>(Op, Wo, Wo, Wo, Wo, Wo, Wo,
                                        (float*)d_out);
}

// round 4
// speedup vs baseline: 6.6357x; 1.0842x over previous
#include <cuda_runtime.h>
#include <cuda_fp16.h>

#define BSZ   2
#define NTOK  2048
#define DIM   1024
#define NHEAD 16
#define HDIM  64

// fp16 hi/lo scratch
__device__ __half g_xh[4096 * 1024],  g_xl[4096 * 1024];
__device__ __half g_wh[4096 * 1024],  g_wl[4096 * 1024];   // rows: Qlb,Qla,Klb,Kla,Vlb,Vla (512 ea), Wo (1024)
__device__ __half g_qkvh[3 * 4096 * 1024], g_qkvl[3 * 4096 * 1024];
__device__ __half g_oh[4096 * 1024],  g_ol[4096 * 1024];

// ---------------- primitives ----------------------------------------------
__device__ __forceinline__ void split2v(float x, float y, __half2& h, __half2& l) {
    h = __floats2half2_rn(x, y);
    float2 f = __half22float2(h);
    l = __floats2half2_rn(x - f.x, y - f.y);
}
__device__ __forceinline__ void mma16(float* c, const unsigned* a,
                                      unsigned b0, unsigned b1) {
    asm volatile(
        "mma.sync.aligned.m16n8k16.row.col.f32.f16.f16.f32 "
        "{%0,%1,%2,%3}, {%4,%5,%6,%7}, {%8,%9}, {%0,%1,%2,%3};"
        : "+f"(c[0]), "+f"(c[1]), "+f"(c[2]), "+f"(c[3])
        : "r"(a[0]), "r"(a[1]), "r"(a[2]), "r"(a[3]), "r"(b0), "r"(b1));
}
__device__ __forceinline__ void ldsm4(unsigned* r, unsigned addr) {
    asm volatile("ldmatrix.sync.aligned.m8n8.x4.shared.b16 {%0,%1,%2,%3}, [%4];"
        : "=r"(r[0]), "=r"(r[1]), "=r"(r[2]), "=r"(r[3]) : "r"(addr));
}
__device__ __forceinline__ void ldsm2(unsigned& r0, unsigned& r1, unsigned addr) {
    asm volatile("ldmatrix.sync.aligned.m8n8.x2.shared.b16 {%0,%1}, [%2];"
        : "=r"(r0), "=r"(r1) : "r"(addr));
}
__device__ __forceinline__ void ldsm2t(unsigned& r0, unsigned& r1, unsigned addr) {
    asm volatile("ldmatrix.sync.aligned.m8n8.x2.trans.shared.b16 {%0,%1}, [%2];"
        : "=r"(r0), "=r"(r1) : "r"(addr));
}
__device__ __forceinline__ void cpa(unsigned dst, const void* src) {
    asm volatile("cp.async.cg.shared.global [%0], [%1], 16;" :: "r"(dst), "l"(src));
}
__device__ __forceinline__ void cpcommit() { asm volatile("cp.async.commit_group;"); }
template <int N> __device__ __forceinline__ void cpwait() {
    asm volatile("cp.async.wait_group %0;" :: "n"(N));
}

// ---------------- pre-split passes -----------------------------------------
__global__ void presplit_x(const float* __restrict__ x,
                           __half* __restrict__ xh, __half* __restrict__ xl) {
    int id = blockIdx.x * 256 + threadIdx.x;           // float4 id, 1M total
    float4 v = reinterpret_cast<const float4*>(x)[id];
    __half2 h0, l0, h1, l1;
    split2v(v.x, v.y, h0, l0);
    split2v(v.z, v.w, h1, l1);
    reinterpret_cast<__half2*>(xh)[id * 2]     = h0;
    reinterpret_cast<__half2*>(xh)[id * 2 + 1] = h1;
    reinterpret_cast<__half2*>(xl)[id * 2]     = l0;
    reinterpret_cast<__half2*>(xl)[id * 2 + 1] = l1;
}

__global__ void presplit_w(const float* __restrict__ W0, const float* __restrict__ W1,
                           const float* __restrict__ W2, const float* __restrict__ W3,
                           const float* __restrict__ W4, const float* __restrict__ W5,
                           const float* __restrict__ W6,
                           __half* __restrict__ wh, __half* __restrict__ wl) {
    int id  = blockIdx.x * 256 + threadIdx.x;          // float4 id, 1M total
    int row = id >> 8;                                 // 256 float4 per row
    int q   = id & 255;
    const float* src;
    int rr;
    if (row < 3072) {
        int t = row >> 9;
        src = (t == 0) ? W0 : (t == 1) ? W1 : (t == 2) ? W2
            : (t == 3) ? W3 : (t == 4) ? W4 : W5;
        rr = row & 511;
    } else {
        src = W6; rr = row - 3072;
    }
    float4 v = reinterpret_cast<const float4*>(src + (size_t)rr * DIM)[q];
    __half2 h0, l0, h1, l1;
    split2v(v.x, v.y, h0, l0);
    split2v(v.z, v.w, h1, l1);
    reinterpret_cast<__half2*>(wh)[id * 2]     = h0;
    reinterpret_cast<__half2*>(wh)[id * 2 + 1] = h1;
    reinterpret_cast<__half2*>(wl)[id * 2]     = l0;
    reinterpret_cast<__half2*>(wl)[id * 2 + 1] = l1;
}

// ---------------------------------------------------------------------------
// fp16x3 GEMM, cp.async double-buffered. C[4096, N] = A[4096,1024] * W^T.
// MODE 0: QKV (N=3072, W rows 0..3071), epilogue scatters hi/lo fp16 QKV.
// MODE 1: out-proj (N=1024, W rows 3072..4095), epilogue stores fp32.
// Tile 128x128xBK32, 8 warps (64x32 each).
// ---------------------------------------------------------------------------
#define GSTR 40   // half stride: 80B rows (16B aligned, LDSM conflict-free)

template <int MODE>
__global__ void __launch_bounds__(256, 2)
gemm_hl(const __half* __restrict__ Ah, const __half* __restrict__ Al,
        const __half* __restrict__ Wh, const __half* __restrict__ Wl,
        __half* __restrict__ Ch, __half* __restrict__ Cl,
        float* __restrict__ Cf) {
    extern __shared__ __half smx[];
    __half* sAh = smx;               // [2][128*40]
    __half* sAl = smx + 10240;
    __half* sBh = smx + 20480;
    __half* sBl = smx + 30720;

    const int tid  = threadIdx.x;
    const int lane = tid & 31;
    const int wid  = tid >> 5;
    const int wm   = (wid >> 2) * 64;
    const int wn   = (wid & 3) * 32;
    const int row0 = blockIdx.y * 128;
    const int col0 = blockIdx.x * 128;
    const int wrow0 = (MODE == 0) ? col0 : (col0 + 3072);

    const unsigned aAh = (unsigned)__cvta_generic_to_shared(sAh);
    const unsigned aAl = (unsigned)__cvta_generic_to_shared(sAl);
    const unsigned aBh = (unsigned)__cvta_generic_to_shared(sBh);
    const unsigned aBl = (unsigned)__cvta_generic_to_shared(sBl);

    const int crow = tid >> 2;          // chunk row (first of 2)
    const int ckc  = tid & 3;           // chunk col within row

    auto issue = [&](int s) {
        const int buf = s & 1;
        const int k0 = s * 32;
        #pragma unroll
        for (int i = 0; i < 2; i++) {
            int row = crow + i * 64;
            unsigned doff = buf * 10240 + row * 80 + ckc * 16;
            size_t soffA = (size_t)(row0 + row) * DIM + k0 + ckc * 8;
            size_t soffB = (size_t)(wrow0 + row) * DIM + k0 + ckc * 8;
            cpa(aAh + doff, Ah + soffA);
            cpa(aAl + doff, Al + soffA);
            cpa(aBh + doff, Wh + soffB);
            cpa(aBl + doff, Wl + soffB);
        }
    };

    float acc[4][4][4] = {};

    issue(0); cpcommit();

    #pragma unroll 1
    for (int s = 0; s < 32; s++) {
        if (s < 31) { issue(s + 1); cpcommit(); cpwait<1>(); }
        else        { cpwait<0>(); }
        __syncthreads();

        const unsigned bufoff = (s & 1) * 10240;
        #pragma unroll
        for (int ks = 0; ks < 2; ks++) {
            unsigned bh[4][2], bl[4][2];
            #pragma unroll
            for (int ni = 0; ni < 4; ni++) {
                unsigned off = bufoff + ((wn + ni * 8 + (lane & 7)) * GSTR
                                         + ks * 16 + ((lane >> 3) & 1) * 8) * 2;
                ldsm2(bh[ni][0], bh[ni][1], aBh + off);
                ldsm2(bl[ni][0], bl[ni][1], aBl + off);
            }
            #pragma unroll
            for (int mi = 0; mi < 4; mi++) {
                unsigned ah[4], al[4];
                unsigned off = bufoff + ((wm + mi * 16 + (lane & 15)) * GSTR
                                         + ks * 16 + (lane >> 4) * 8) * 2;
                ldsm4(ah, aAh + off);
                ldsm4(al, aAl + off);
                #pragma unroll
                for (int ni = 0; ni < 4; ni++) {
                    mma16(acc[mi][ni], ah, bh[ni][0], bh[ni][1]);
                    mma16(acc[mi][ni], al, bh[ni][0], bh[ni][1]);
                    mma16(acc[mi][ni], ah, bl[ni][0], bl[ni][1]);
                }
            }
        }
        __syncthreads();
    }

    // epilogue
    #pragma unroll
    for (int mi = 0; mi < 4; mi++) {
        int r = row0 + wm + mi * 16 + (lane >> 2);
        #pragma unroll
        for (int ni = 0; ni < 4; ni++) {
            int c = col0 + wn + ni * 8 + 2 * (lane & 3);
            if (MODE == 0) {
                __half2 h0, l0, h1, l1;
                split2v(acc[mi][ni][0], acc[mi][ni][1], h0, l0);
                split2v(acc[mi][ni][2], acc[mi][ni][3], h1, l1);
                int m = c >> 10, j = c & 1023;
                int hh = j >> 6, e = j & 63;
                int b = r >> 11, n = r & 2047;
                size_t idx = ((((size_t)(m * 2 + b) * 16 + hh) * NTOK) + n) * HDIM + e;
                *reinterpret_cast<__half2*>(&Ch[idx])            = h0;
                *reinterpret_cast<__half2*>(&Cl[idx])            = l0;
                *reinterpret_cast<__half2*>(&Ch[idx + 8 * HDIM]) = h1;
                *reinterpret_cast<__half2*>(&Cl[idx + 8 * HDIM]) = l1;
            } else {
                float2 v0 = make_float2(acc[mi][ni][0], acc[mi][ni][1]);
                float2 v1 = make_float2(acc[mi][ni][2], acc[mi][ni][3]);
                *reinterpret_cast<float2*>(&Cf[(size_t)r * DIM + c])       = v0;
                *reinterpret_cast<float2*>(&Cf[(size_t)(r + 8) * DIM + c]) = v1;
            }
        }
    }
}

// ---------------------------------------------------------------------------
// fp16x3 flash attention, cp.async double-buffered K/V, fp16 hi/lo I/O.
// Block = (qtile 64, head, batch), 4 warps; warp w: query rows [w*16, w*16+16).
// ---------------------------------------------------------------------------
#define KSTR 72   // half stride: 144B rows

__global__ void __launch_bounds__(128)
attn_hl(const __half* __restrict__ QKVh, const __half* __restrict__ QKVl,
        __half* __restrict__ Oh, __half* __restrict__ Ol) {
    extern __shared__ __half sma[];
    // halfs offsets
    __half* sQh = sma;                   // 64*72
    __half* sQl = sma + 4608;
    __half* sKh = sma + 9216;            // [2][64*72]
    __half* sKl = sma + 18432;
    __half* sVh = sma + 27648;
    __half* sVl = sma + 36864;

    const int qt  = blockIdx.x;
    const int h   = blockIdx.y;
    const int b   = blockIdx.z;
    const bool causal = (h < 8);
    const int tid  = threadIdx.x;
    const int lane = tid & 31;
    const int w    = tid >> 5;
    const int quad = lane & 3;
    const int gpr  = lane >> 2;

    const size_t hb = ((size_t)b * 16 + h) * NTOK * HDIM;
    const __half* Qgh = QKVh + hb;
    const __half* Qgl = QKVl + hb;
    const __half* Kgh = QKVh + 2 * 4096 * 1024 / 2 + hb;   // mat 1 offset = 2*16*2048*64
    const __half* Kgl = QKVl + 2 * 4096 * 1024 / 2 + hb;
    const __half* Vgh = QKVh + 4 * 4096 * 1024 / 2 + hb;   // mat 2
    const __half* Vgl = QKVl + 4 * 4096 * 1024 / 2 + hb;

    const unsigned aQh = (unsigned)__cvta_generic_to_shared(sQh);
    const unsigned aQl = (unsigned)__cvta_generic_to_shared(sQl);
    const unsigned aKh = (unsigned)__cvta_generic_to_shared(sKh);
    const unsigned aKl = (unsigned)__cvta_generic_to_shared(sKl);
    const unsigned aVh = (unsigned)__cvta_generic_to_shared(sVh);
    const unsigned aVl = (unsigned)__cvta_generic_to_shared(sVl);

    const int kt0 = causal ? 0 : qt;
    const int kt1 = causal ? qt : (NTOK / 64 - 1);

    auto issue_kv = [&](int kt, int buf) {
        #pragma unroll
        for (int i = 0; i < 4; i++) {
            int c = tid + i * 128;        // 0..511
            int key = c >> 3, ec = c & 7;
            size_t soff = (size_t)(kt * 64 + key) * HDIM + ec * 8;
            unsigned doff = buf * 9216 + key * 144 + ec * 16;
            cpa(aKh + doff, Kgh + soff);
            cpa(aKl + doff, Kgl + soff);
            cpa(aVh + doff, Vgh + soff);
            cpa(aVl + doff, Vgl + soff);
        }
    };

    // prologue: Q tile + first KV tile, one group
    #pragma unroll
    for (int i = 0; i < 4; i++) {
        int c = tid + i * 128;
        int row = c >> 3, ec = c & 7;
        size_t soff = (size_t)(qt * 64 + row) * HDIM + ec * 8;
        unsigned doff = row * 144 + ec * 16;
        cpa(aQh + doff, Qgh + soff);
        cpa(aQl + doff, Qgl + soff);
    }
    issue_kv(kt0, 0);
    cpcommit();

    const int qrow0 = qt * 64 + w * 16;
    const int gq0 = qrow0 + gpr;
    const int gq1 = gq0 + 8;

    unsigned qh[4][4], ql[4][4];
    float o[8][4] = {};
    float m0 = -1e30f, m1 = -1e30f, l0 = 0.f, l1 = 0.f;

    #pragma unroll 1
    for (int kt = kt0; kt <= kt1; kt++) {
        const int buf = (kt - kt0) & 1;
        if (kt < kt1) { issue_kv(kt + 1, buf ^ 1); cpcommit(); cpwait<1>(); }
        else          { cpwait<0>(); }
        __syncthreads();

        if (kt == kt0) {
            #pragma unroll
            for (int ks = 0; ks < 4; ks++) {
                unsigned off = ((w * 16 + (lane & 15)) * KSTR
                                + ks * 16 + (lane >> 4) * 8) * 2;
                ldsm4(qh[ks], aQh + off);
                ldsm4(ql[ks], aQl + off);
            }
        }

        const unsigned kvoff = buf * 9216;

        // S = Q K^T
        float sc[8][4] = {};
        #pragma unroll
        for (int ks = 0; ks < 4; ks++) {
            #pragma unroll
            for (int ni = 0; ni < 8; ni++) {
                unsigned off = kvoff + ((ni * 8 + (lane & 7)) * KSTR
                                        + ks * 16 + ((lane >> 3) & 1) * 8) * 2;
                unsigned kh0, kh1, kl0, kl1;
                ldsm2(kh0, kh1, aKh + off);
                ldsm2(kl0, kl1, aKl + off);
                mma16(sc[ni], qh[ks], kh0, kh1);
                mma16(sc[ni], ql[ks], kh0, kh1);
                mma16(sc[ni], qh[ks], kl0, kl1);
            }
        }

        // scale + mask
        const bool diag = (kt == qt);
        #pragma unroll
        for (int ni = 0; ni < 8; ni++) {
            #pragma unroll
            for (int j = 0; j < 4; j++) sc[ni][j] *= 0.125f;
            if (diag) {
                int gk = kt * 64 + ni * 8 + 2 * quad;
                if (!(causal ? (gk     <= gq0) : (gk     >= gq0))) sc[ni][0] = -1e30f;
                if (!(causal ? (gk + 1 <= gq0) : (gk + 1 >= gq0))) sc[ni][1] = -1e30f;
                if (!(causal ? (gk     <= gq1) : (gk     >= gq1))) sc[ni][2] = -1e30f;
                if (!(causal ? (gk + 1 <= gq1) : (gk + 1 >= gq1))) sc[ni][3] = -1e30f;
            }
        }

        // online softmax
        float mt0 = -1e30f, mt1 = -1e30f;
        #pragma unroll
        for (int ni = 0; ni < 8; ni++) {
            mt0 = fmaxf(mt0, fmaxf(sc[ni][0], sc[ni][1]));
            mt1 = fmaxf(mt1, fmaxf(sc[ni][2], sc[ni][3]));
        }
        mt0 = fmaxf(mt0, __shfl_xor_sync(0xffffffffu, mt0, 1));
        mt0 = fmaxf(mt0, __shfl_xor_sync(0xffffffffu, mt0, 2));
        mt1 = fmaxf(mt1, __shfl_xor_sync(0xffffffffu, mt1, 1));
        mt1 = fmaxf(mt1, __shfl_xor_sync(0xffffffffu, mt1, 2));

        float mn0 = fmaxf(m0, mt0), mn1 = fmaxf(m1, mt1);
        float cr0 = __expf(m0 - mn0), cr1 = __expf(m1 - mn1);
        m0 = mn0; m1 = mn1;

        float ls0 = 0.f, ls1 = 0.f;
        #pragma unroll
        for (int ni = 0; ni < 8; ni++) {
            sc[ni][0] = __expf(sc[ni][0] - mn0);
            sc[ni][1] = __expf(sc[ni][1] - mn0);
            sc[ni][2] = __expf(sc[ni][2] - mn1);
            sc[ni][3] = __expf(sc[ni][3] - mn1);
            ls0 += sc[ni][0] + sc[ni][1];
            ls1 += sc[ni][2] + sc[ni][3];
        }
        ls0 += __shfl_xor_sync(0xffffffffu, ls0, 1);
        ls0 += __shfl_xor_sync(0xffffffffu, ls0, 2);
        ls1 += __shfl_xor_sync(0xffffffffu, ls1, 1);
        ls1 += __shfl_xor_sync(0xffffffffu, ls1, 2);
        l0 = l0 * cr0 + ls0;
        l1 = l1 * cr1 + ls1;

        #pragma unroll
        for (int ni = 0; ni < 8; ni++) {
            o[ni][0] *= cr0; o[ni][1] *= cr0;
            o[ni][2] *= cr1; o[ni][3] *= cr1;
        }

        // PV (P C-frags == A-frags)
        #pragma unroll
        for (int ks = 0; ks < 4; ks++) {
            unsigned ph[4], pl[4];
            {
                __half2 hh, ll;
                split2v(sc[2*ks][0],   sc[2*ks][1],   hh, ll);
                ph[0] = *reinterpret_cast<unsigned*>(&hh);
                pl[0] = *reinterpret_cast<unsigned*>(&ll);
                split2v(sc[2*ks][2],   sc[2*ks][3],   hh, ll);
                ph[1] = *reinterpret_cast<unsigned*>(&hh);
                pl[1] = *reinterpret_cast<unsigned*>(&ll);
                split2v(sc[2*ks+1][0], sc[2*ks+1][1], hh, ll);
                ph[2] = *reinterpret_cast<unsigned*>(&hh);
                pl[2] = *reinterpret_cast<unsigned*>(&ll);
                split2v(sc[2*ks+1][2], sc[2*ks+1][3], hh, ll);
                ph[3] = *reinterpret_cast<unsigned*>(&hh);
                pl[3] = *reinterpret_cast<unsigned*>(&ll);
            }
            unsigned vrow = ks * 16 + (lane & 15);
            #pragma unroll
            for (int ni = 0; ni < 8; ni++) {
                unsigned off = kvoff + (vrow * KSTR + ni * 8) * 2;
                unsigned vh0, vh1, vl0, vl1;
                ldsm2t(vh0, vh1, aVh + off);
                ldsm2t(vl0, vl1, aVl + off);
                mma16(o[ni], ph, vh0, vh1);
                mma16(o[ni], pl, vh0, vh1);
                mma16(o[ni], ph, vl0, vl1);
            }
        }
        __syncthreads();
    }

    // write O as hi/lo fp16 (flat (B,H,N,E))
    float inv0 = 1.f / l0, inv1 = 1.f / l1;
    const size_t ob = ((size_t)b * 16 + h) * NTOK * HDIM;
    #pragma unroll
    for (int ni = 0; ni < 8; ni++) {
        int c = ni * 8 + 2 * quad;
        __half2 h0, l0h, h1, l1h;
        split2v(o[ni][0] * inv0, o[ni][1] * inv0, h0, l0h);
        split2v(o[ni][2] * inv1, o[ni][3] * inv1, h1, l1h);
        size_t i0 = ob + (size_t)gq0 * HDIM + c;
        size_t i1 = ob + (size_t)gq1 * HDIM + c;
        *reinterpret_cast<__half2*>(&Oh[i0]) = h0;
        *reinterpret_cast<__half2*>(&Ol[i0]) = l0h;
        *reinterpret_cast<__half2*>(&Oh[i1]) = h1;
        *reinterpret_cast<__half2*>(&Ol[i1]) = l1h;
    }
}

// ---------------------------------------------------------------------------
extern "C" void kernel_launch(void* const* d_in, const int* in_sizes, int n_in,
                              void* d_out, int out_size) {
    const float* x     = (const float*)d_in[0];
    const float* Wq_lb = (const float*)d_in[1];
    const float* Wk_lb = (const float*)d_in[2];
    const float* Wv_lb = (const float*)d_in[3];
    const float* Wq_la = (const float*)d_in[4];
    const float* Wk_la = (const float*)d_in[5];
    const float* Wv_la = (const float*)d_in[6];
    const float* Wo    = (const float*)d_in[7];

    __half *xh, *xl, *wh, *wl, *qkvh, *qkvl, *oh, *ol;
    cudaGetSymbolAddress((void**)&xh, g_xh);
    cudaGetSymbolAddress((void**)&xl, g_xl);
    cudaGetSymbolAddress((void**)&wh, g_wh);
    cudaGetSymbolAddress((void**)&wl, g_wl);
    cudaGetSymbolAddress((void**)&qkvh, g_qkvh);
    cudaGetSymbolAddress((void**)&qkvl, g_qkvl);
    cudaGetSymbolAddress((void**)&oh, g_oh);
    cudaGetSymbolAddress((void**)&ol, g_ol);

    presplit_x<<<4096, 256>>>(x, xh, xl);
    presplit_w<<<4096, 256>>>(Wq_lb, Wq_la, Wk_lb, Wk_la, Wv_lb, Wv_la, Wo,
                              wh, wl);

    cudaFuncSetAttribute(gemm_hl<0>,
                         cudaFuncAttributeMaxDynamicSharedMemorySize, 81920);
    cudaFuncSetAttribute(gemm_hl<1>,
                         cudaFuncAttributeMaxDynamicSharedMemorySize, 81920);
    cudaFuncSetAttribute(attn_hl,
                         cudaFuncAttributeMaxDynamicSharedMemorySize, 92160);

    gemm_hl<0><<<dim3(24, 32), 256, 81920>>>(xh, xl, wh, wl, qkvh, qkvl, nullptr);
    attn_hl<<<dim3(NTOK / 64, NHEAD, BSZ), 128, 92160>>>(qkvh, qkvl, oh, ol);
    gemm_hl<1><<<dim3(8, 32), 256, 81920>>>(oh, ol, wh, wl, nullptr, nullptr,
                                            (float*)d_out);
}

// round 5
// speedup vs baseline: 6.8562x; 1.0332x over previous
#include <cuda_runtime.h>
#include <cuda_fp16.h>

#define BSZ   2
#define NTOK  2048
#define DIM   1024
#define NHEAD 16
#define HDIM  64

// fp16 hi/lo scratch
__device__ __half g_xh[4096 * 1024],  g_xl[4096 * 1024];
__device__ __half g_wh[4096 * 1024],  g_wl[4096 * 1024];
__device__ __half g_qkvh[3 * 4096 * 1024], g_qkvl[3 * 4096 * 1024];
__device__ __half g_oh[4096 * 1024],  g_ol[4096 * 1024];

// ---------------- primitives ----------------------------------------------
__device__ __forceinline__ void split2v(float x, float y, __half2& h, __half2& l) {
    h = __floats2half2_rn(x, y);
    float2 f = __half22float2(h);
    l = __floats2half2_rn(x - f.x, y - f.y);
}
__device__ __forceinline__ void mma16(float* c, const unsigned* a,
                                      unsigned b0, unsigned b1) {
    asm volatile(
        "mma.sync.aligned.m16n8k16.row.col.f32.f16.f16.f32 "
        "{%0,%1,%2,%3}, {%4,%5,%6,%7}, {%8,%9}, {%0,%1,%2,%3};"
        : "+f"(c[0]), "+f"(c[1]), "+f"(c[2]), "+f"(c[3])
        : "r"(a[0]), "r"(a[1]), "r"(a[2]), "r"(a[3]), "r"(b0), "r"(b1));
}
__device__ __forceinline__ void ldsm4(unsigned* r, unsigned addr) {
    asm volatile("ldmatrix.sync.aligned.m8n8.x4.shared.b16 {%0,%1,%2,%3}, [%4];"
        : "=r"(r[0]), "=r"(r[1]), "=r"(r[2]), "=r"(r[3]) : "r"(addr));
}
__device__ __forceinline__ void ldsm4t(unsigned* r, unsigned addr) {
    asm volatile("ldmatrix.sync.aligned.m8n8.x4.trans.shared.b16 {%0,%1,%2,%3}, [%4];"
        : "=r"(r[0]), "=r"(r[1]), "=r"(r[2]), "=r"(r[3]) : "r"(addr));
}
__device__ __forceinline__ void cpa(unsigned dst, const void* src) {
    asm volatile("cp.async.cg.shared.global [%0], [%1], 16;" :: "r"(dst), "l"(src));
}
__device__ __forceinline__ void cpcommit() { asm volatile("cp.async.commit_group;"); }
template <int N> __device__ __forceinline__ void cpwait() {
    asm volatile("cp.async.wait_group %0;" :: "n"(N));
}

// ---------------- pre-split passes -----------------------------------------
__global__ void presplit_x(const float* __restrict__ x,
                           __half* __restrict__ xh, __half* __restrict__ xl) {
    int id = blockIdx.x * 256 + threadIdx.x;
    float4 v = reinterpret_cast<const float4*>(x)[id];
    __half2 h0, l0, h1, l1;
    split2v(v.x, v.y, h0, l0);
    split2v(v.z, v.w, h1, l1);
    reinterpret_cast<__half2*>(xh)[id * 2]     = h0;
    reinterpret_cast<__half2*>(xh)[id * 2 + 1] = h1;
    reinterpret_cast<__half2*>(xl)[id * 2]     = l0;
    reinterpret_cast<__half2*>(xl)[id * 2 + 1] = l1;
}

__global__ void presplit_w(const float* __restrict__ W0, const float* __restrict__ W1,
                           const float* __restrict__ W2, const float* __restrict__ W3,
                           const float* __restrict__ W4, const float* __restrict__ W5,
                           const float* __restrict__ W6,
                           __half* __restrict__ wh, __half* __restrict__ wl) {
    int id  = blockIdx.x * 256 + threadIdx.x;
    int row = id >> 8;
    int q   = id & 255;
    const float* src;
    int rr;
    if (row < 3072) {
        int t = row >> 9;
        src = (t == 0) ? W0 : (t == 1) ? W1 : (t == 2) ? W2
            : (t == 3) ? W3 : (t == 4) ? W4 : W5;
        rr = row & 511;
    } else {
        src = W6; rr = row - 3072;
    }
    float4 v = reinterpret_cast<const float4*>(src + (size_t)rr * DIM)[q];
    __half2 h0, l0, h1, l1;
    split2v(v.x, v.y, h0, l0);
    split2v(v.z, v.w, h1, l1);
    reinterpret_cast<__half2*>(wh)[id * 2]     = h0;
    reinterpret_cast<__half2*>(wh)[id * 2 + 1] = h1;
    reinterpret_cast<__half2*>(wl)[id * 2]     = l0;
    reinterpret_cast<__half2*>(wl)[id * 2 + 1] = l1;
}

// ---------------------------------------------------------------------------
// fp16x3 GEMM, cp.async double-buffered. C[4096, N] = A[4096,1024] * W^T.
// ---------------------------------------------------------------------------
#define GSTR 40

template <int MODE>
__global__ void __launch_bounds__(256, 2)
gemm_hl(const __half* __restrict__ Ah, const __half* __restrict__ Al,
        const __half* __restrict__ Wh, const __half* __restrict__ Wl,
        __half* __restrict__ Ch, __half* __restrict__ Cl,
        float* __restrict__ Cf) {
    extern __shared__ __half smx[];
    __half* sAh = smx;               // [2][128*40]
    __half* sAl = smx + 10240;
    __half* sBh = smx + 20480;
    __half* sBl = smx + 30720;

    const int tid  = threadIdx.x;
    const int lane = tid & 31;
    const int wid  = tid >> 5;
    const int wm   = (wid >> 2) * 64;
    const int wn   = (wid & 3) * 32;
    const int row0 = blockIdx.y * 128;
    const int col0 = blockIdx.x * 128;
    const int wrow0 = (MODE == 0) ? col0 : (col0 + 3072);

    const unsigned aAh = (unsigned)__cvta_generic_to_shared(sAh);
    const unsigned aAl = (unsigned)__cvta_generic_to_shared(sAl);
    const unsigned aBh = (unsigned)__cvta_generic_to_shared(sBh);
    const unsigned aBl = (unsigned)__cvta_generic_to_shared(sBl);

    const int crow = tid >> 2;
    const int ckc  = tid & 3;

    auto issue = [&](int s) {
        const int buf = s & 1;
        const int k0 = s * 32;
        #pragma unroll
        for (int i = 0; i < 2; i++) {
            int row = crow + i * 64;
            unsigned doff = buf * 10240 + row * 80 + ckc * 16;
            size_t soffA = (size_t)(row0 + row) * DIM + k0 + ckc * 8;
            size_t soffB = (size_t)(wrow0 + row) * DIM + k0 + ckc * 8;
            cpa(aAh + doff, Ah + soffA);
            cpa(aAl + doff, Al + soffA);
            cpa(aBh + doff, Wh + soffB);
            cpa(aBl + doff, Wl + soffB);
        }
    };

    float acc[4][4][4] = {};

    issue(0); cpcommit();

    #pragma unroll 1
    for (int s = 0; s < 32; s++) {
        if (s < 31) { issue(s + 1); cpcommit(); cpwait<1>(); }
        else        { cpwait<0>(); }
        __syncthreads();

        const unsigned bufoff = (s & 1) * 10240;
        #pragma unroll
        for (int ks = 0; ks < 2; ks++) {
            unsigned bh[2][4], bl[2][4];
            #pragma unroll
            for (int np = 0; np < 2; np++) {
                unsigned off = bufoff +
                    ((wn + np * 16 + (lane >> 4) * 8 + (lane & 7)) * GSTR
                     + ks * 16 + ((lane >> 3) & 1) * 8) * 2;
                ldsm4(bh[np], aBh + off);
                ldsm4(bl[np], aBl + off);
            }
            #pragma unroll
            for (int mi = 0; mi < 4; mi++) {
                unsigned ah[4], al[4];
                unsigned off = bufoff + ((wm + mi * 16 + (lane & 15)) * GSTR
                                         + ks * 16 + (lane >> 4) * 8) * 2;
                ldsm4(ah, aAh + off);
                ldsm4(al, aAl + off);
                #pragma unroll
                for (int ni = 0; ni < 4; ni++) {
                    unsigned b0h = bh[ni >> 1][(ni & 1) * 2];
                    unsigned b1h = bh[ni >> 1][(ni & 1) * 2 + 1];
                    unsigned b0l = bl[ni >> 1][(ni & 1) * 2];
                    unsigned b1l = bl[ni >> 1][(ni & 1) * 2 + 1];
                    mma16(acc[mi][ni], ah, b0h, b1h);
                    mma16(acc[mi][ni], al, b0h, b1h);
                    mma16(acc[mi][ni], ah, b0l, b1l);
                }
            }
        }
        __syncthreads();
    }

    // epilogue
    #pragma unroll
    for (int mi = 0; mi < 4; mi++) {
        int r = row0 + wm + mi * 16 + (lane >> 2);
        #pragma unroll
        for (int ni = 0; ni < 4; ni++) {
            int c = col0 + wn + ni * 8 + 2 * (lane & 3);
            if (MODE == 0) {
                __half2 h0, l0, h1, l1;
                split2v(acc[mi][ni][0], acc[mi][ni][1], h0, l0);
                split2v(acc[mi][ni][2], acc[mi][ni][3], h1, l1);
                int m = c >> 10, j = c & 1023;
                int hh = j >> 6, e = j & 63;
                int b = r >> 11, n = r & 2047;
                size_t idx = ((((size_t)(m * 2 + b) * 16 + hh) * NTOK) + n) * HDIM + e;
                *reinterpret_cast<__half2*>(&Ch[idx])            = h0;
                *reinterpret_cast<__half2*>(&Cl[idx])            = l0;
                *reinterpret_cast<__half2*>(&Ch[idx + 8 * HDIM]) = h1;
                *reinterpret_cast<__half2*>(&Cl[idx + 8 * HDIM]) = l1;
            } else {
                float2 v0 = make_float2(acc[mi][ni][0], acc[mi][ni][1]);
                float2 v1 = make_float2(acc[mi][ni][2], acc[mi][ni][3]);
                *reinterpret_cast<float2*>(&Cf[(size_t)r * DIM + c])       = v0;
                *reinterpret_cast<float2*>(&Cf[(size_t)(r + 8) * DIM + c]) = v1;
            }
        }
    }
}

// ---------------------------------------------------------------------------
// fp16x3 flash attention v3: qtile=128, 8 warps, ldsm.x4, 2 CTAs/SM.
// Block = (qtile, head, batch); warp w owns query rows [w*16, w*16+16).
// ---------------------------------------------------------------------------
// smem byte layout (dynamic):
#define AQH   0u
#define AQL   18432u
#define ABUF  36864u
#define ABUFSZ 36864u
#define AKH   0u
#define AKL   9216u
#define AVH   18432u
#define AVL   27648u
#define ATTN_SMEM 110592
#define KSTR  72

__global__ void __launch_bounds__(256, 2)
attn_hl(const __half* __restrict__ QKVh, const __half* __restrict__ QKVl,
        __half* __restrict__ Oh, __half* __restrict__ Ol) {
    extern __shared__ __half sma[];
    const unsigned sbase = (unsigned)__cvta_generic_to_shared(sma);

    const int qt  = blockIdx.x;     // 0..15 (128-row q tiles)
    const int h   = blockIdx.y;
    const int b   = blockIdx.z;
    const bool causal = (h < 8);
    const int tid  = threadIdx.x;
    const int lane = tid & 31;
    const int w    = tid >> 5;      // 0..7
    const int quad = lane & 3;
    const int gpr  = lane >> 2;

    const size_t hb = ((size_t)b * 16 + h) * NTOK * HDIM;
    const __half* Qgh = QKVh + hb;
    const __half* Qgl = QKVl + hb;
    const __half* Kgh = QKVh + 2 * 2048 * 1024 + hb;
    const __half* Kgl = QKVl + 2 * 2048 * 1024 + hb;
    const __half* Vgh = QKVh + 4 * 2048 * 1024 + hb;
    const __half* Vgl = QKVl + 4 * 2048 * 1024 + hb;

    const int kt0 = causal ? 0 : (2 * qt);
    const int kt1 = causal ? (2 * qt + 1) : (NTOK / 64 - 1);

    auto issue_kv = [&](int kt, int buf) {
        #pragma unroll
        for (int i = 0; i < 2; i++) {
            int c = tid + i * 256;            // 0..511
            int key = c >> 3, ec = c & 7;
            size_t soff = (size_t)(kt * 64 + key) * HDIM + ec * 8;
            unsigned doff = sbase + ABUF + buf * ABUFSZ + key * 144 + ec * 16;
            cpa(doff + AKH, Kgh + soff);
            cpa(doff + AKL, Kgl + soff);
            cpa(doff + AVH, Vgh + soff);
            cpa(doff + AVL, Vgl + soff);
        }
    };

    // prologue: Q tile (128 rows) + first KV tile in one group
    #pragma unroll
    for (int i = 0; i < 4; i++) {
        int c = tid + i * 256;                // 0..1023
        int row = c >> 3, ec = c & 7;
        size_t soff = (size_t)(qt * 128 + row) * HDIM + ec * 8;
        unsigned doff = row * 144 + ec * 16;
        cpa(sbase + AQH + doff, Qgh + soff);
        cpa(sbase + AQL + doff, Qgl + soff);
    }
    issue_kv(kt0, 0);
    cpcommit();

    const int gq0 = qt * 128 + w * 16 + gpr;
    const int gq1 = gq0 + 8;

    float o[8][4] = {};
    float m0 = -1e30f, m1 = -1e30f, l0 = 0.f, l1 = 0.f;

    #pragma unroll 1
    for (int kt = kt0; kt <= kt1; kt++) {
        const int buf = (kt - kt0) & 1;
        if (kt < kt1) { issue_kv(kt + 1, buf ^ 1); cpcommit(); cpwait<1>(); }
        else          { cpwait<0>(); }
        __syncthreads();

        const unsigned kvb = sbase + ABUF + buf * ABUFSZ;

        // S = Q K^T
        float sc[8][4] = {};
        #pragma unroll
        for (int ks = 0; ks < 4; ks++) {
            unsigned qh[4], ql[4];
            unsigned qoff = ((w * 16 + (lane & 15)) * KSTR
                             + ks * 16 + (lane >> 4) * 8) * 2;
            ldsm4(qh, sbase + AQH + qoff);
            ldsm4(ql, sbase + AQL + qoff);
            #pragma unroll
            for (int np = 0; np < 4; np++) {
                unsigned kh[4], kl[4];
                unsigned koff = ((np * 16 + (lane >> 4) * 8 + (lane & 7)) * KSTR
                                 + ks * 16 + ((lane >> 3) & 1) * 8) * 2;
                ldsm4(kh, kvb + AKH + koff);
                ldsm4(kl, kvb + AKL + koff);
                mma16(sc[2 * np],     qh, kh[0], kh[1]);
                mma16(sc[2 * np],     ql, kh[0], kh[1]);
                mma16(sc[2 * np],     qh, kl[0], kl[1]);
                mma16(sc[2 * np + 1], qh, kh[2], kh[3]);
                mma16(sc[2 * np + 1], ql, kh[2], kh[3]);
                mma16(sc[2 * np + 1], qh, kl[2], kl[3]);
            }
        }

        // scale + mask (diag when this ktile overlaps the q tile)
        const bool diag = ((kt >> 1) == qt);
        #pragma unroll
        for (int ni = 0; ni < 8; ni++) {
            #pragma unroll
            for (int j = 0; j < 4; j++) sc[ni][j] *= 0.125f;
            if (diag) {
                int gk = kt * 64 + ni * 8 + 2 * quad;
                if (!(causal ? (gk     <= gq0) : (gk     >= gq0))) sc[ni][0] = -1e30f;
                if (!(causal ? (gk + 1 <= gq0) : (gk + 1 >= gq0))) sc[ni][1] = -1e30f;
                if (!(causal ? (gk     <= gq1) : (gk     >= gq1))) sc[ni][2] = -1e30f;
                if (!(causal ? (gk + 1 <= gq1) : (gk + 1 >= gq1))) sc[ni][3] = -1e30f;
            }
        }

        // online softmax
        float mt0 = -1e30f, mt1 = -1e30f;
        #pragma unroll
        for (int ni = 0; ni < 8; ni++) {
            mt0 = fmaxf(mt0, fmaxf(sc[ni][0], sc[ni][1]));
            mt1 = fmaxf(mt1, fmaxf(sc[ni][2], sc[ni][3]));
        }
        mt0 = fmaxf(mt0, __shfl_xor_sync(0xffffffffu, mt0, 1));
        mt0 = fmaxf(mt0, __shfl_xor_sync(0xffffffffu, mt0, 2));
        mt1 = fmaxf(mt1, __shfl_xor_sync(0xffffffffu, mt1, 1));
        mt1 = fmaxf(mt1, __shfl_xor_sync(0xffffffffu, mt1, 2));

        float mn0 = fmaxf(m0, mt0), mn1 = fmaxf(m1, mt1);
        float cr0 = __expf(m0 - mn0), cr1 = __expf(m1 - mn1);
        m0 = mn0; m1 = mn1;

        float ls0 = 0.f, ls1 = 0.f;
        #pragma unroll
        for (int ni = 0; ni < 8; ni++) {
            sc[ni][0] = __expf(sc[ni][0] - mn0);
            sc[ni][1] = __expf(sc[ni][1] - mn0);
            sc[ni][2] = __expf(sc[ni][2] - mn1);
            sc[ni][3] = __expf(sc[ni][3] - mn1);
            ls0 += sc[ni][0] + sc[ni][1];
            ls1 += sc[ni][2] + sc[ni][3];
        }
        ls0 += __shfl_xor_sync(0xffffffffu, ls0, 1);
        ls0 += __shfl_xor_sync(0xffffffffu, ls0, 2);
        ls1 += __shfl_xor_sync(0xffffffffu, ls1, 1);
        ls1 += __shfl_xor_sync(0xffffffffu, ls1, 2);
        l0 = l0 * cr0 + ls0;
        l1 = l1 * cr1 + ls1;

        #pragma unroll
        for (int ni = 0; ni < 8; ni++) {
            o[ni][0] *= cr0; o[ni][1] *= cr0;
            o[ni][2] *= cr1; o[ni][3] *= cr1;
        }

        // PV (P C-frags == A-frags)
        #pragma unroll
        for (int ks = 0; ks < 4; ks++) {
            unsigned ph[4], pl[4];
            {
                __half2 hh, ll;
                split2v(sc[2*ks][0],   sc[2*ks][1],   hh, ll);
                ph[0] = *reinterpret_cast<unsigned*>(&hh);
                pl[0] = *reinterpret_cast<unsigned*>(&ll);
                split2v(sc[2*ks][2],   sc[2*ks][3],   hh, ll);
                ph[1] = *reinterpret_cast<unsigned*>(&hh);
                pl[1] = *reinterpret_cast<unsigned*>(&ll);
                split2v(sc[2*ks+1][0], sc[2*ks+1][1], hh, ll);
                ph[2] = *reinterpret_cast<unsigned*>(&hh);
                pl[2] = *reinterpret_cast<unsigned*>(&ll);
                split2v(sc[2*ks+1][2], sc[2*ks+1][3], hh, ll);
                ph[3] = *reinterpret_cast<unsigned*>(&hh);
                pl[3] = *reinterpret_cast<unsigned*>(&ll);
            }
            #pragma unroll
            for (int np = 0; np < 4; np++) {
                unsigned vh[4], vl[4];
                unsigned voff = ((ks * 16 + (lane & 15)) * KSTR
                                 + np * 16 + (lane >> 4) * 8) * 2;
                ldsm4t(vh, kvb + AVH + voff);
                ldsm4t(vl, kvb + AVL + voff);
                mma16(o[2 * np],     ph, vh[0], vh[1]);
                mma16(o[2 * np],     pl, vh[0], vh[1]);
                mma16(o[2 * np],     ph, vl[0], vl[1]);
                mma16(o[2 * np + 1], ph, vh[2], vh[3]);
                mma16(o[2 * np + 1], pl, vh[2], vh[3]);
                mma16(o[2 * np + 1], ph, vl[2], vl[3]);
            }
        }
        __syncthreads();
    }

    // write O as hi/lo fp16 (flat (B,H,N,E))
    float inv0 = 1.f / l0, inv1 = 1.f / l1;
    const size_t ob = ((size_t)b * 16 + h) * NTOK * HDIM;
    #pragma unroll
    for (int ni = 0; ni < 8; ni++) {
        int c = ni * 8 + 2 * quad;
        __half2 h0, l0h, h1, l1h;
        split2v(o[ni][0] * inv0, o[ni][1] * inv0, h0, l0h);
        split2v(o[ni][2] * inv1, o[ni][3] * inv1, h1, l1h);
        size_t i0 = ob + (size_t)gq0 * HDIM + c;
        size_t i1 = ob + (size_t)gq1 * HDIM + c;
        *reinterpret_cast<__half2*>(&Oh[i0]) = h0;
        *reinterpret_cast<__half2*>(&Ol[i0]) = l0h;
        *reinterpret_cast<__half2*>(&Oh[i1]) = h1;
        *reinterpret_cast<__half2*>(&Ol[i1]) = l1h;
    }
}

// ---------------------------------------------------------------------------
extern "C" void kernel_launch(void* const* d_in, const int* in_sizes, int n_in,
                              void* d_out, int out_size) {
    const float* x     = (const float*)d_in[0];
    const float* Wq_lb = (const float*)d_in[1];
    const float* Wk_lb = (const float*)d_in[2];
    const float* Wv_lb = (const float*)d_in[3];
    const float* Wq_la = (const float*)d_in[4];
    const float* Wk_la = (const float*)d_in[5];
    const float* Wv_la = (const float*)d_in[6];
    const float* Wo    = (const float*)d_in[7];

    __half *xh, *xl, *wh, *wl, *qkvh, *qkvl, *oh, *ol;
    cudaGetSymbolAddress((void**)&xh, g_xh);
    cudaGetSymbolAddress((void**)&xl, g_xl);
    cudaGetSymbolAddress((void**)&wh, g_wh);
    cudaGetSymbolAddress((void**)&wl, g_wl);
    cudaGetSymbolAddress((void**)&qkvh, g_qkvh);
    cudaGetSymbolAddress((void**)&qkvl, g_qkvl);
    cudaGetSymbolAddress((void**)&oh, g_oh);
    cudaGetSymbolAddress((void**)&ol, g_ol);

    presplit_x<<<4096, 256>>>(x, xh, xl);
    presplit_w<<<4096, 256>>>(Wq_lb, Wq_la, Wk_lb, Wk_la, Wv_lb, Wv_la, Wo,
                              wh, wl);

    cudaFuncSetAttribute(gemm_hl<0>,
                         cudaFuncAttributeMaxDynamicSharedMemorySize, 81920);
    cudaFuncSetAttribute(gemm_hl<1>,
                         cudaFuncAttributeMaxDynamicSharedMemorySize, 81920);
    cudaFuncSetAttribute(attn_hl,
                         cudaFuncAttributeMaxDynamicSharedMemorySize, ATTN_SMEM);

    gemm_hl<0><<<dim3(24, 32), 256, 81920>>>(xh, xl, wh, wl, qkvh, qkvl, nullptr);
    attn_hl<<<dim3(NTOK / 128, NHEAD, BSZ), 256, ATTN_SMEM>>>(qkvh, qkvl, oh, ol);
    gemm_hl<1><<<dim3(8, 32), 256, 81920>>>(oh, ol, wh, wl, nullptr, nullptr,
                                            (float*)d_out);
}

// round 6
// speedup vs baseline: 9.3715x; 1.3669x over previous
#include <cuda_runtime.h>
#include <cuda_fp16.h>

#define BSZ   2
#define NTOK  2048
#define DIM   1024
#define NHEAD 16
#define HDIM  64

// fp16 scratch: A-side operands keep hi+lo; B-side (weights, K, V) hi only.
__device__ __half g_xh[4096 * 1024],  g_xl[4096 * 1024];
__device__ __half g_wh[4096 * 1024];
__device__ __half g_qkvh[3 * 4096 * 1024], g_qkvl[3 * 4096 * 1024];
__device__ __half g_oh[4096 * 1024],  g_ol[4096 * 1024];

// ---------------- primitives ----------------------------------------------
__device__ __forceinline__ void split2v(float x, float y, __half2& h, __half2& l) {
    h = __floats2half2_rn(x, y);
    float2 f = __half22float2(h);
    l = __floats2half2_rn(x - f.x, y - f.y);
}
__device__ __forceinline__ void mma16(float* c, const unsigned* a,
                                      unsigned b0, unsigned b1) {
    asm volatile(
        "mma.sync.aligned.m16n8k16.row.col.f32.f16.f16.f32 "
        "{%0,%1,%2,%3}, {%4,%5,%6,%7}, {%8,%9}, {%0,%1,%2,%3};"
        : "+f"(c[0]), "+f"(c[1]), "+f"(c[2]), "+f"(c[3])
        : "r"(a[0]), "r"(a[1]), "r"(a[2]), "r"(a[3]), "r"(b0), "r"(b1));
}
__device__ __forceinline__ void ldsm4(unsigned* r, unsigned addr) {
    asm volatile("ldmatrix.sync.aligned.m8n8.x4.shared.b16 {%0,%1,%2,%3}, [%4];"
        : "=r"(r[0]), "=r"(r[1]), "=r"(r[2]), "=r"(r[3]) : "r"(addr));
}
__device__ __forceinline__ void ldsm4t(unsigned* r, unsigned addr) {
    asm volatile("ldmatrix.sync.aligned.m8n8.x4.trans.shared.b16 {%0,%1,%2,%3}, [%4];"
        : "=r"(r[0]), "=r"(r[1]), "=r"(r[2]), "=r"(r[3]) : "r"(addr));
}
__device__ __forceinline__ void cpa(unsigned dst, const void* src) {
    asm volatile("cp.async.cg.shared.global [%0], [%1], 16;" :: "r"(dst), "l"(src));
}
__device__ __forceinline__ void cpcommit() { asm volatile("cp.async.commit_group;"); }
template <int N> __device__ __forceinline__ void cpwait() {
    asm volatile("cp.async.wait_group %0;" :: "n"(N));
}

// ---------------- pre-split passes -----------------------------------------
__global__ void presplit_x(const float* __restrict__ x,
                           __half* __restrict__ xh, __half* __restrict__ xl) {
    int id = blockIdx.x * 256 + threadIdx.x;
    float4 v = reinterpret_cast<const float4*>(x)[id];
    __half2 h0, l0, h1, l1;
    split2v(v.x, v.y, h0, l0);
    split2v(v.z, v.w, h1, l1);
    reinterpret_cast<__half2*>(xh)[id * 2]     = h0;
    reinterpret_cast<__half2*>(xh)[id * 2 + 1] = h1;
    reinterpret_cast<__half2*>(xl)[id * 2]     = l0;
    reinterpret_cast<__half2*>(xl)[id * 2 + 1] = l1;
}

__global__ void presplit_w(const float* __restrict__ W0, const float* __restrict__ W1,
                           const float* __restrict__ W2, const float* __restrict__ W3,
                           const float* __restrict__ W4, const float* __restrict__ W5,
                           const float* __restrict__ W6,
                           __half* __restrict__ wh) {
    int id  = blockIdx.x * 256 + threadIdx.x;
    int row = id >> 8;
    int q   = id & 255;
    const float* src;
    int rr;
    if (row < 3072) {
        int t = row >> 9;
        src = (t == 0) ? W0 : (t == 1) ? W1 : (t == 2) ? W2
            : (t == 3) ? W3 : (t == 4) ? W4 : W5;
        rr = row & 511;
    } else {
        src = W6; rr = row - 3072;
    }
    float4 v = reinterpret_cast<const float4*>(src + (size_t)rr * DIM)[q];
    __half2 h0 = __floats2half2_rn(v.x, v.y);
    __half2 h1 = __floats2half2_rn(v.z, v.w);
    reinterpret_cast<__half2*>(wh)[id * 2]     = h0;
    reinterpret_cast<__half2*>(wh)[id * 2 + 1] = h1;
}

// ---------------------------------------------------------------------------
// fp16x2 GEMM: C = (A_hi + A_lo) * W_hi^T, cp.async double-buffered.
// MODE 0: QKV (N=3072), scatter hi/lo epilogue. MODE 1: out-proj, fp32 out.
// Tile 128x128xBK32, 8 warps (64x32 each).
// ---------------------------------------------------------------------------
#define GSTR 40

template <int MODE>
__global__ void __launch_bounds__(256, 2)
gemm_hl(const __half* __restrict__ Ah, const __half* __restrict__ Al,
        const __half* __restrict__ Wh,
        __half* __restrict__ Ch, __half* __restrict__ Cl,
        float* __restrict__ Cf) {
    extern __shared__ __half smx[];
    __half* sAh = smx;               // [2][128*40]
    __half* sAl = smx + 10240;
    __half* sBh = smx + 20480;

    const int tid  = threadIdx.x;
    const int lane = tid & 31;
    const int wid  = tid >> 5;
    const int wm   = (wid >> 2) * 64;
    const int wn   = (wid & 3) * 32;
    const int row0 = blockIdx.y * 128;
    const int col0 = blockIdx.x * 128;
    const int wrow0 = (MODE == 0) ? col0 : (col0 + 3072);

    const unsigned aAh = (unsigned)__cvta_generic_to_shared(sAh);
    const unsigned aAl = (unsigned)__cvta_generic_to_shared(sAl);
    const unsigned aBh = (unsigned)__cvta_generic_to_shared(sBh);

    const int crow = tid >> 2;
    const int ckc  = tid & 3;

    auto issue = [&](int s) {
        const int buf = s & 1;
        const int k0 = s * 32;
        #pragma unroll
        for (int i = 0; i < 2; i++) {
            int row = crow + i * 64;
            unsigned doff = buf * 10240 + row * 80 + ckc * 16;
            size_t soffA = (size_t)(row0 + row) * DIM + k0 + ckc * 8;
            size_t soffB = (size_t)(wrow0 + row) * DIM + k0 + ckc * 8;
            cpa(aAh + doff, Ah + soffA);
            cpa(aAl + doff, Al + soffA);
            cpa(aBh + doff, Wh + soffB);
        }
    };

    float acc[4][4][4] = {};

    issue(0); cpcommit();

    #pragma unroll 1
    for (int s = 0; s < 32; s++) {
        if (s < 31) { issue(s + 1); cpcommit(); cpwait<1>(); }
        else        { cpwait<0>(); }
        __syncthreads();

        const unsigned bufoff = (s & 1) * 10240;
        #pragma unroll
        for (int ks = 0; ks < 2; ks++) {
            unsigned bh[2][4];
            #pragma unroll
            for (int np = 0; np < 2; np++) {
                unsigned off = bufoff +
                    ((wn + np * 16 + (lane >> 4) * 8 + (lane & 7)) * GSTR
                     + ks * 16 + ((lane >> 3) & 1) * 8) * 2;
                ldsm4(bh[np], aBh + off);
            }
            #pragma unroll
            for (int mi = 0; mi < 4; mi++) {
                unsigned ah[4], al[4];
                unsigned off = bufoff + ((wm + mi * 16 + (lane & 15)) * GSTR
                                         + ks * 16 + (lane >> 4) * 8) * 2;
                ldsm4(ah, aAh + off);
                ldsm4(al, aAl + off);
                #pragma unroll
                for (int ni = 0; ni < 4; ni++) {
                    unsigned b0 = bh[ni >> 1][(ni & 1) * 2];
                    unsigned b1 = bh[ni >> 1][(ni & 1) * 2 + 1];
                    mma16(acc[mi][ni], ah, b0, b1);
                    mma16(acc[mi][ni], al, b0, b1);
                }
            }
        }
        __syncthreads();
    }

    // epilogue
    #pragma unroll
    for (int mi = 0; mi < 4; mi++) {
        int r = row0 + wm + mi * 16 + (lane >> 2);
        #pragma unroll
        for (int ni = 0; ni < 4; ni++) {
            int c = col0 + wn + ni * 8 + 2 * (lane & 3);
            if (MODE == 0) {
                __half2 h0, l0, h1, l1;
                split2v(acc[mi][ni][0], acc[mi][ni][1], h0, l0);
                split2v(acc[mi][ni][2], acc[mi][ni][3], h1, l1);
                int m = c >> 10, j = c & 1023;
                int hh = j >> 6, e = j & 63;
                int b = r >> 11, n = r & 2047;
                size_t idx = ((((size_t)(m * 2 + b) * 16 + hh) * NTOK) + n) * HDIM + e;
                *reinterpret_cast<__half2*>(&Ch[idx])            = h0;
                *reinterpret_cast<__half2*>(&Cl[idx])            = l0;
                *reinterpret_cast<__half2*>(&Ch[idx + 8 * HDIM]) = h1;
                *reinterpret_cast<__half2*>(&Cl[idx + 8 * HDIM]) = l1;
            } else {
                float2 v0 = make_float2(acc[mi][ni][0], acc[mi][ni][1]);
                float2 v1 = make_float2(acc[mi][ni][2], acc[mi][ni][3]);
                *reinterpret_cast<float2*>(&Cf[(size_t)r * DIM + c])       = v0;
                *reinterpret_cast<float2*>(&Cf[(size_t)(r + 8) * DIM + c]) = v1;
            }
        }
    }
}

// ---------------------------------------------------------------------------
// fp16x2 flash attention: qtile=128, 8 warps, 2 CTAs/SM.
// S = (Q_hi+Q_lo) K_hi^T ; O += (P_hi+P_lo) V_hi.  K/V hi only in smem.
// ---------------------------------------------------------------------------
#define AQH   0u
#define AQL   18432u
#define ABUF  36864u
#define ABUFSZ 18432u
#define AKH   0u
#define AVH   9216u
#define ATTN_SMEM 73728
#define KSTR  72

__global__ void __launch_bounds__(256, 2)
attn_hl(const __half* __restrict__ QKVh, const __half* __restrict__ QKVl,
        __half* __restrict__ Oh, __half* __restrict__ Ol) {
    extern __shared__ __half sma[];
    const unsigned sbase = (unsigned)__cvta_generic_to_shared(sma);

    const int qt  = blockIdx.x;     // 0..15 (128-row q tiles)
    const int h   = blockIdx.y;
    const int b   = blockIdx.z;
    const bool causal = (h < 8);
    const int tid  = threadIdx.x;
    const int lane = tid & 31;
    const int w    = tid >> 5;
    const int quad = lane & 3;
    const int gpr  = lane >> 2;

    const size_t hb = ((size_t)b * 16 + h) * NTOK * HDIM;
    const __half* Qgh = QKVh + hb;
    const __half* Qgl = QKVl + hb;
    const __half* Kgh = QKVh + 2 * 2048 * 1024 + hb;
    const __half* Vgh = QKVh + 4 * 2048 * 1024 + hb;

    const int kt0 = causal ? 0 : (2 * qt);
    const int kt1 = causal ? (2 * qt + 1) : (NTOK / 64 - 1);

    auto issue_kv = [&](int kt, int buf) {
        #pragma unroll
        for (int i = 0; i < 2; i++) {
            int c = tid + i * 256;            // 0..511
            int key = c >> 3, ec = c & 7;
            size_t soff = (size_t)(kt * 64 + key) * HDIM + ec * 8;
            unsigned doff = sbase + ABUF + buf * ABUFSZ + key * 144 + ec * 16;
            cpa(doff + AKH, Kgh + soff);
            cpa(doff + AVH, Vgh + soff);
        }
    };

    // prologue: Q tile (128 rows, hi+lo) + first KV tile
    #pragma unroll
    for (int i = 0; i < 4; i++) {
        int c = tid + i * 256;
        int row = c >> 3, ec = c & 7;
        size_t soff = (size_t)(qt * 128 + row) * HDIM + ec * 8;
        unsigned doff = row * 144 + ec * 16;
        cpa(sbase + AQH + doff, Qgh + soff);
        cpa(sbase + AQL + doff, Qgl + soff);
    }
    issue_kv(kt0, 0);
    cpcommit();

    const int gq0 = qt * 128 + w * 16 + gpr;
    const int gq1 = gq0 + 8;

    float o[8][4] = {};
    float m0 = -1e30f, m1 = -1e30f, l0 = 0.f, l1 = 0.f;

    #pragma unroll 1
    for (int kt = kt0; kt <= kt1; kt++) {
        const int buf = (kt - kt0) & 1;
        if (kt < kt1) { issue_kv(kt + 1, buf ^ 1); cpcommit(); cpwait<1>(); }
        else          { cpwait<0>(); }
        __syncthreads();

        const unsigned kvb = sbase + ABUF + buf * ABUFSZ;

        // S = Q K^T
        float sc[8][4] = {};
        #pragma unroll
        for (int ks = 0; ks < 4; ks++) {
            unsigned qh[4], ql[4];
            unsigned qoff = ((w * 16 + (lane & 15)) * KSTR
                             + ks * 16 + (lane >> 4) * 8) * 2;
            ldsm4(qh, sbase + AQH + qoff);
            ldsm4(ql, sbase + AQL + qoff);
            #pragma unroll
            for (int np = 0; np < 4; np++) {
                unsigned kh[4];
                unsigned koff = ((np * 16 + (lane >> 4) * 8 + (lane & 7)) * KSTR
                                 + ks * 16 + ((lane >> 3) & 1) * 8) * 2;
                ldsm4(kh, kvb + AKH + koff);
                mma16(sc[2 * np],     qh, kh[0], kh[1]);
                mma16(sc[2 * np],     ql, kh[0], kh[1]);
                mma16(sc[2 * np + 1], qh, kh[2], kh[3]);
                mma16(sc[2 * np + 1], ql, kh[2], kh[3]);
            }
        }

        // scale + mask
        const bool diag = ((kt >> 1) == qt);
        #pragma unroll
        for (int ni = 0; ni < 8; ni++) {
            #pragma unroll
            for (int j = 0; j < 4; j++) sc[ni][j] *= 0.125f;
            if (diag) {
                int gk = kt * 64 + ni * 8 + 2 * quad;
                if (!(causal ? (gk     <= gq0) : (gk     >= gq0))) sc[ni][0] = -1e30f;
                if (!(causal ? (gk + 1 <= gq0) : (gk + 1 >= gq0))) sc[ni][1] = -1e30f;
                if (!(causal ? (gk     <= gq1) : (gk     >= gq1))) sc[ni][2] = -1e30f;
                if (!(causal ? (gk + 1 <= gq1) : (gk + 1 >= gq1))) sc[ni][3] = -1e30f;
            }
        }

        // online softmax
        float mt0 = -1e30f, mt1 = -1e30f;
        #pragma unroll
        for (int ni = 0; ni < 8; ni++) {
            mt0 = fmaxf(mt0, fmaxf(sc[ni][0], sc[ni][1]));
            mt1 = fmaxf(mt1, fmaxf(sc[ni][2], sc[ni][3]));
        }
        mt0 = fmaxf(mt0, __shfl_xor_sync(0xffffffffu, mt0, 1));
        mt0 = fmaxf(mt0, __shfl_xor_sync(0xffffffffu, mt0, 2));
        mt1 = fmaxf(mt1, __shfl_xor_sync(0xffffffffu, mt1, 1));
        mt1 = fmaxf(mt1, __shfl_xor_sync(0xffffffffu, mt1, 2));

        float mn0 = fmaxf(m0, mt0), mn1 = fmaxf(m1, mt1);
        float cr0 = __expf(m0 - mn0), cr1 = __expf(m1 - mn1);
        m0 = mn0; m1 = mn1;

        float ls0 = 0.f, ls1 = 0.f;
        #pragma unroll
        for (int ni = 0; ni < 8; ni++) {
            sc[ni][0] = __expf(sc[ni][0] - mn0);
            sc[ni][1] = __expf(sc[ni][1] - mn0);
            sc[ni][2] = __expf(sc[ni][2] - mn1);
            sc[ni][3] = __expf(sc[ni][3] - mn1);
            ls0 += sc[ni][0] + sc[ni][1];
            ls1 += sc[ni][2] + sc[ni][3];
        }
        ls0 += __shfl_xor_sync(0xffffffffu, ls0, 1);
        ls0 += __shfl_xor_sync(0xffffffffu, ls0, 2);
        ls1 += __shfl_xor_sync(0xffffffffu, ls1, 1);
        ls1 += __shfl_xor_sync(0xffffffffu, ls1, 2);
        l0 = l0 * cr0 + ls0;
        l1 = l1 * cr1 + ls1;

        #pragma unroll
        for (int ni = 0; ni < 8; ni++) {
            o[ni][0] *= cr0; o[ni][1] *= cr0;
            o[ni][2] *= cr1; o[ni][3] *= cr1;
        }

        // PV: O += (P_hi + P_lo) * V_hi
        #pragma unroll
        for (int ks = 0; ks < 4; ks++) {
            unsigned ph[4], pl[4];
            {
                __half2 hh, ll;
                split2v(sc[2*ks][0],   sc[2*ks][1],   hh, ll);
                ph[0] = *reinterpret_cast<unsigned*>(&hh);
                pl[0] = *reinterpret_cast<unsigned*>(&ll);
                split2v(sc[2*ks][2],   sc[2*ks][3],   hh, ll);
                ph[1] = *reinterpret_cast<unsigned*>(&hh);
                pl[1] = *reinterpret_cast<unsigned*>(&ll);
                split2v(sc[2*ks+1][0], sc[2*ks+1][1], hh, ll);
                ph[2] = *reinterpret_cast<unsigned*>(&hh);
                pl[2] = *reinterpret_cast<unsigned*>(&ll);
                split2v(sc[2*ks+1][2], sc[2*ks+1][3], hh, ll);
                ph[3] = *reinterpret_cast<unsigned*>(&hh);
                pl[3] = *reinterpret_cast<unsigned*>(&ll);
            }
            #pragma unroll
            for (int np = 0; np < 4; np++) {
                unsigned vh[4];
                unsigned voff = ((ks * 16 + (lane & 15)) * KSTR
                                 + np * 16 + (lane >> 4) * 8) * 2;
                ldsm4t(vh, kvb + AVH + voff);
                mma16(o[2 * np],     ph, vh[0], vh[1]);
                mma16(o[2 * np],     pl, vh[0], vh[1]);
                mma16(o[2 * np + 1], ph, vh[2], vh[3]);
                mma16(o[2 * np + 1], pl, vh[2], vh[3]);
            }
        }
        __syncthreads();
    }

    // write O as hi/lo fp16 (flat (B,H,N,E))
    float inv0 = 1.f / l0, inv1 = 1.f / l1;
    const size_t ob = ((size_t)b * 16 + h) * NTOK * HDIM;
    #pragma unroll
    for (int ni = 0; ni < 8; ni++) {
        int c = ni * 8 + 2 * quad;
        __half2 h0, l0h, h1, l1h;
        split2v(o[ni][0] * inv0, o[ni][1] * inv0, h0, l0h);
        split2v(o[ni][2] * inv1, o[ni][3] * inv1, h1, l1h);
        size_t i0 = ob + (size_t)gq0 * HDIM + c;
        size_t i1 = ob + (size_t)gq1 * HDIM + c;
        *reinterpret_cast<__half2*>(&Oh[i0]) = h0;
        *reinterpret_cast<__half2*>(&Ol[i0]) = l0h;
        *reinterpret_cast<__half2*>(&Oh[i1]) = h1;
        *reinterpret_cast<__half2*>(&Ol[i1]) = l1h;
    }
}

// ---------------------------------------------------------------------------
extern "C" void kernel_launch(void* const* d_in, const int* in_sizes, int n_in,
                              void* d_out, int out_size) {
    const float* x     = (const float*)d_in[0];
    const float* Wq_lb = (const float*)d_in[1];
    const float* Wk_lb = (const float*)d_in[2];
    const float* Wv_lb = (const float*)d_in[3];
    const float* Wq_la = (const float*)d_in[4];
    const float* Wk_la = (const float*)d_in[5];
    const float* Wv_la = (const float*)d_in[6];
    const float* Wo    = (const float*)d_in[7];

    __half *xh, *xl, *wh, *qkvh, *qkvl, *oh, *ol;
    cudaGetSymbolAddress((void**)&xh, g_xh);
    cudaGetSymbolAddress((void**)&xl, g_xl);
    cudaGetSymbolAddress((void**)&wh, g_wh);
    cudaGetSymbolAddress((void**)&qkvh, g_qkvh);
    cudaGetSymbolAddress((void**)&qkvl, g_qkvl);
    cudaGetSymbolAddress((void**)&oh, g_oh);
    cudaGetSymbolAddress((void**)&ol, g_ol);

    presplit_x<<<4096, 256>>>(x, xh, xl);
    presplit_w<<<4096, 256>>>(Wq_lb, Wq_la, Wk_lb, Wk_la, Wv_lb, Wv_la, Wo, wh);

    cudaFuncSetAttribute(gemm_hl<0>,
                         cudaFuncAttributeMaxDynamicSharedMemorySize, 61440);
    cudaFuncSetAttribute(gemm_hl<1>,
                         cudaFuncAttributeMaxDynamicSharedMemorySize, 61440);
    cudaFuncSetAttribute(attn_hl,
                         cudaFuncAttributeMaxDynamicSharedMemorySize, ATTN_SMEM);

    gemm_hl<0><<<dim3(24, 32), 256, 61440>>>(xh, xl, wh, qkvh, qkvl, nullptr);
    attn_hl<<<dim3(NTOK / 128, NHEAD, BSZ), 256, ATTN_SMEM>>>(qkvh, qkvl, oh, ol);
    gemm_hl<1><<<dim3(8, 32), 256, 61440>>>(oh, ol, wh, nullptr, nullptr,
                                            (float*)d_out);
}

// round 8
// speedup vs baseline: 10.0904x; 1.0767x over previous
#include <cuda_runtime.h>
#include <cuda_fp16.h>

#define BSZ   2
#define NTOK  2048
#define DIM   1024
#define NHEAD 16
#define HDIM  64

// fp16 scratch: A-side operands keep hi+lo; B-side (weights, K, V) hi only.
__device__ __half g_xh[4096 * 1024],  g_xl[4096 * 1024];
__device__ __half g_wh[4096 * 1024];
__device__ __half g_qkvh[3 * 4096 * 1024], g_qkvl[3 * 4096 * 1024];
__device__ __half g_oh[4096 * 1024],  g_ol[4096 * 1024];

// Q pre-scale: 1/sqrt(64) * log2(e)  (softmax runs in log2 domain)
#define QSCALE 0.18033688011112042f

// ---------------- primitives ----------------------------------------------
__device__ __forceinline__ void split2v(float x, float y, __half2& h, __half2& l) {
    h = __floats2half2_rn(x, y);
    float2 f = __half22float2(h);
    l = __floats2half2_rn(x - f.x, y - f.y);
}
__device__ __forceinline__ float ex2(float x) {
    float r;
    asm("ex2.approx.f32 %0, %1;" : "=f"(r) : "f"(x));
    return r;
}
__device__ __forceinline__ void mma16(float* c, const unsigned* a,
                                      unsigned b0, unsigned b1) {
    asm volatile(
        "mma.sync.aligned.m16n8k16.row.col.f32.f16.f16.f32 "
        "{%0,%1,%2,%3}, {%4,%5,%6,%7}, {%8,%9}, {%0,%1,%2,%3};"
        : "+f"(c[0]), "+f"(c[1]), "+f"(c[2]), "+f"(c[3])
        : "r"(a[0]), "r"(a[1]), "r"(a[2]), "r"(a[3]), "r"(b0), "r"(b1));
}
__device__ __forceinline__ void ldsm4(unsigned* r, unsigned addr) {
    asm volatile("ldmatrix.sync.aligned.m8n8.x4.shared.b16 {%0,%1,%2,%3}, [%4];"
        : "=r"(r[0]), "=r"(r[1]), "=r"(r[2]), "=r"(r[3]) : "r"(addr));
}
__device__ __forceinline__ void ldsm4t(unsigned* r, unsigned addr) {
    asm volatile("ldmatrix.sync.aligned.m8n8.x4.trans.shared.b16 {%0,%1,%2,%3}, [%4];"
        : "=r"(r[0]), "=r"(r[1]), "=r"(r[2]), "=r"(r[3]) : "r"(addr));
}
__device__ __forceinline__ void cpa(unsigned dst, const void* src) {
    asm volatile("cp.async.cg.shared.global [%0], [%1], 16;" :: "r"(dst), "l"(src));
}
__device__ __forceinline__ void cpcommit() { asm volatile("cp.async.commit_group;"); }
template <int N> __device__ __forceinline__ void cpwait() {
    asm volatile("cp.async.wait_group %0;" :: "n"(N));
}

// ---------------- pre-split passes -----------------------------------------
__global__ void presplit_x(const float* __restrict__ x,
                           __half* __restrict__ xh, __half* __restrict__ xl) {
    int id = blockIdx.x * 256 + threadIdx.x;
    float4 v = reinterpret_cast<const float4*>(x)[id];
    __half2 h0, l0, h1, l1;
    split2v(v.x, v.y, h0, l0);
    split2v(v.z, v.w, h1, l1);
    reinterpret_cast<__half2*>(xh)[id * 2]     = h0;
    reinterpret_cast<__half2*>(xh)[id * 2 + 1] = h1;
    reinterpret_cast<__half2*>(xl)[id * 2]     = l0;
    reinterpret_cast<__half2*>(xl)[id * 2 + 1] = l1;
}

__global__ void presplit_w(const float* __restrict__ W0, const float* __restrict__ W1,
                           const float* __restrict__ W2, const float* __restrict__ W3,
                           const float* __restrict__ W4, const float* __restrict__ W5,
                           const float* __restrict__ W6,
                           __half* __restrict__ wh) {
    int id  = blockIdx.x * 256 + threadIdx.x;
    int row = id >> 8;
    int q   = id & 255;
    const float* src;
    int rr;
    if (row < 3072) {
        int t = row >> 9;
        src = (t == 0) ? W0 : (t == 1) ? W1 : (t == 2) ? W2
            : (t == 3) ? W3 : (t == 4) ? W4 : W5;
        rr = row & 511;
    } else {
        src = W6; rr = row - 3072;
    }
    float4 v = reinterpret_cast<const float4*>(src + (size_t)rr * DIM)[q];
    __half2 h0 = __floats2half2_rn(v.x, v.y);
    __half2 h1 = __floats2half2_rn(v.z, v.w);
    reinterpret_cast<__half2*>(wh)[id * 2]     = h0;
    reinterpret_cast<__half2*>(wh)[id * 2 + 1] = h1;
}

// ---------------------------------------------------------------------------
// fp16x2 GEMM: C = (A_hi + A_lo) * W_hi^T, cp.async double-buffered.
// MODE 0: QKV (N=3072), scatter hi/lo epilogue, Q cols pre-scaled by QSCALE.
// MODE 1: out-proj, fp32 out. Tile 128x128xBK32, 8 warps (64x32 each).
// ---------------------------------------------------------------------------
#define GSTR 40

template <int MODE>
__global__ void __launch_bounds__(256, 2)
gemm_hl(const __half* __restrict__ Ah, const __half* __restrict__ Al,
        const __half* __restrict__ Wh,
        __half* __restrict__ Ch, __half* __restrict__ Cl,
        float* __restrict__ Cf) {
    extern __shared__ __half smx[];
    __half* sAh = smx;               // [2][128*40]
    __half* sAl = smx + 10240;
    __half* sBh = smx + 20480;

    const int tid  = threadIdx.x;
    const int lane = tid & 31;
    const int wid  = tid >> 5;
    const int wm   = (wid >> 2) * 64;
    const int wn   = (wid & 3) * 32;
    const int row0 = blockIdx.y * 128;
    const int col0 = blockIdx.x * 128;
    const int wrow0 = (MODE == 0) ? col0 : (col0 + 3072);

    const unsigned aAh = (unsigned)__cvta_generic_to_shared(sAh);
    const unsigned aAl = (unsigned)__cvta_generic_to_shared(sAl);
    const unsigned aBh = (unsigned)__cvta_generic_to_shared(sBh);

    const int crow = tid >> 2;
    const int ckc  = tid & 3;

    auto issue = [&](int s) {
        const int buf = s & 1;
        const int k0 = s * 32;
        #pragma unroll
        for (int i = 0; i < 2; i++) {
            int row = crow + i * 64;
            unsigned doff = buf * 10240 + row * 80 + ckc * 16;
            size_t soffA = (size_t)(row0 + row) * DIM + k0 + ckc * 8;
            size_t soffB = (size_t)(wrow0 + row) * DIM + k0 + ckc * 8;
            cpa(aAh + doff, Ah + soffA);
            cpa(aAl + doff, Al + soffA);
            cpa(aBh + doff, Wh + soffB);
        }
    };

    float acc[4][4][4] = {};

    issue(0); cpcommit();

    #pragma unroll 1
    for (int s = 0; s < 32; s++) {
        if (s < 31) { issue(s + 1); cpcommit(); cpwait<1>(); }
        else        { cpwait<0>(); }
        __syncthreads();

        const unsigned bufoff = (s & 1) * 10240;
        #pragma unroll
        for (int ks = 0; ks < 2; ks++) {
            unsigned bh[2][4];
            #pragma unroll
            for (int np = 0; np < 2; np++) {
                unsigned off = bufoff +
                    ((wn + np * 16 + (lane >> 4) * 8 + (lane & 7)) * GSTR
                     + ks * 16 + ((lane >> 3) & 1) * 8) * 2;
                ldsm4(bh[np], aBh + off);
            }
            #pragma unroll
            for (int mi = 0; mi < 4; mi++) {
                unsigned ah[4], al[4];
                unsigned off = bufoff + ((wm + mi * 16 + (lane & 15)) * GSTR
                                         + ks * 16 + (lane >> 4) * 8) * 2;
                ldsm4(ah, aAh + off);
                ldsm4(al, aAl + off);
                #pragma unroll
                for (int ni = 0; ni < 4; ni++) {
                    unsigned b0 = bh[ni >> 1][(ni & 1) * 2];
                    unsigned b1 = bh[ni >> 1][(ni & 1) * 2 + 1];
                    mma16(acc[mi][ni], ah, b0, b1);
                    mma16(acc[mi][ni], al, b0, b1);
                }
            }
        }
        __syncthreads();
    }

    // epilogue
    #pragma unroll
    for (int mi = 0; mi < 4; mi++) {
        int r = row0 + wm + mi * 16 + (lane >> 2);
        #pragma unroll
        for (int ni = 0; ni < 4; ni++) {
            int c = col0 + wn + ni * 8 + 2 * (lane & 3);
            if (MODE == 0) {
                int m = c >> 10, j = c & 1023;
                float qs = (m == 0) ? QSCALE : 1.0f;   // Q pre-scale
                __half2 h0, l0, h1, l1;
                split2v(acc[mi][ni][0] * qs, acc[mi][ni][1] * qs, h0, l0);
                split2v(acc[mi][ni][2] * qs, acc[mi][ni][3] * qs, h1, l1);
                int hh = j >> 6, e = j & 63;
                int b = r >> 11, n = r & 2047;
                size_t idx = ((((size_t)(m * 2 + b) * 16 + hh) * NTOK) + n) * HDIM + e;
                *reinterpret_cast<__half2*>(&Ch[idx])            = h0;
                *reinterpret_cast<__half2*>(&Cl[idx])            = l0;
                *reinterpret_cast<__half2*>(&Ch[idx + 8 * HDIM]) = h1;
                *reinterpret_cast<__half2*>(&Cl[idx + 8 * HDIM]) = l1;
            } else {
                float2 v0 = make_float2(acc[mi][ni][0], acc[mi][ni][1]);
                float2 v1 = make_float2(acc[mi][ni][2], acc[mi][ni][3]);
                *reinterpret_cast<float2*>(&Cf[(size_t)r * DIM + c])       = v0;
                *reinterpret_cast<float2*>(&Cf[(size_t)(r + 8) * DIM + c]) = v1;
            }
        }
    }
}

// ---------------------------------------------------------------------------
// fp16x2 flash attention, 2-phase load-balanced:
// CTA = (qtile, hpair, batch); phase 0 = head hpair (causal),
// phase 1 = head hpair+8 (anti-causal). Total ktiles per CTA = 34 (constant).
// Softmax in log2 domain (Q pre-scaled by QSCALE in GEMM epilogue).
// ---------------------------------------------------------------------------
#define AQH   0u
#define AQL   18432u
#define ABUF  36864u
#define ABUFSZ 18432u
#define AKH   0u
#define AVH   9216u
#define ATTN_SMEM 73728
#define KSTR  72

__global__ void __launch_bounds__(256, 2)
attn_hl(const __half* __restrict__ QKVh, const __half* __restrict__ QKVl,
        __half* __restrict__ Oh, __half* __restrict__ Ol) {
    extern __shared__ __half sma[];
    const unsigned sbase = (unsigned)__cvta_generic_to_shared(sma);

    const int qt  = blockIdx.x;     // 0..15 (128-row q tiles)
    const int b   = blockIdx.z;
    const int tid  = threadIdx.x;
    const int lane = tid & 31;
    const int w    = tid >> 5;
    const int quad = lane & 3;
    const int gpr  = lane >> 2;

    const int gq0 = qt * 128 + w * 16 + gpr;
    const int gq1 = gq0 + 8;

    #pragma unroll 1
    for (int ph = 0; ph < 2; ph++) {
        const int h = blockIdx.y + ph * 8;
        const bool causal = (ph == 0);

        const size_t hb = ((size_t)b * 16 + h) * NTOK * HDIM;
        const __half* Qgh = QKVh + hb;
        const __half* Qgl = QKVl + hb;
        const __half* Kgh = QKVh + 2 * 2048 * 1024 + hb;
        const __half* Vgh = QKVh + 4 * 2048 * 1024 + hb;

        const int kt0 = causal ? 0 : (2 * qt);
        const int kt1 = causal ? (2 * qt + 1) : (NTOK / 64 - 1);

        auto issue_kv = [&](int kt, int buf) {
            #pragma unroll
            for (int i = 0; i < 2; i++) {
                int c = tid + i * 256;
                int key = c >> 3, ec = c & 7;
                size_t soff = (size_t)(kt * 64 + key) * HDIM + ec * 8;
                unsigned doff = sbase + ABUF + buf * ABUFSZ + key * 144 + ec * 16;
                cpa(doff + AKH, Kgh + soff);
                cpa(doff + AVH, Vgh + soff);
            }
        };

        // prologue: Q tile (hi+lo) + first KV tile, one group
        #pragma unroll
        for (int i = 0; i < 4; i++) {
            int c = tid + i * 256;
            int row = c >> 3, ec = c & 7;
            size_t soff = (size_t)(qt * 128 + row) * HDIM + ec * 8;
            unsigned doff = row * 144 + ec * 16;
            cpa(sbase + AQH + doff, Qgh + soff);
            cpa(sbase + AQL + doff, Qgl + soff);
        }
        issue_kv(kt0, 0);
        cpcommit();

        float o[8][4] = {};
        float m0 = -1e30f, m1 = -1e30f, l0 = 0.f, l1 = 0.f;

        #pragma unroll 1
        for (int kt = kt0; kt <= kt1; kt++) {
            const int buf = (kt - kt0) & 1;
            if (kt < kt1) { issue_kv(kt + 1, buf ^ 1); cpcommit(); cpwait<1>(); }
            else          { cpwait<0>(); }
            __syncthreads();

            const unsigned kvb = sbase + ABUF + buf * ABUFSZ;

            // S = Q K^T (already scaled: log2 domain)
            float sc[8][4] = {};
            #pragma unroll
            for (int ks = 0; ks < 4; ks++) {
                unsigned qh[4], ql[4];
                unsigned qoff = ((w * 16 + (lane & 15)) * KSTR
                                 + ks * 16 + (lane >> 4) * 8) * 2;
                ldsm4(qh, sbase + AQH + qoff);
                ldsm4(ql, sbase + AQL + qoff);
                #pragma unroll
                for (int np = 0; np < 4; np++) {
                    unsigned kh[4];
                    unsigned koff = ((np * 16 + (lane >> 4) * 8 + (lane & 7)) * KSTR
                                     + ks * 16 + ((lane >> 3) & 1) * 8) * 2;
                    ldsm4(kh, kvb + AKH + koff);
                    mma16(sc[2 * np],     qh, kh[0], kh[1]);
                    mma16(sc[2 * np],     ql, kh[0], kh[1]);
                    mma16(sc[2 * np + 1], qh, kh[2], kh[3]);
                    mma16(sc[2 * np + 1], ql, kh[2], kh[3]);
                }
            }

            // mask (diag ktile only)
            const bool diag = ((kt >> 1) == qt);
            if (diag) {
                #pragma unroll
                for (int ni = 0; ni < 8; ni++) {
                    int gk = kt * 64 + ni * 8 + 2 * quad;
                    if (!(causal ? (gk     <= gq0) : (gk     >= gq0))) sc[ni][0] = -1e30f;
                    if (!(causal ? (gk + 1 <= gq0) : (gk + 1 >= gq0))) sc[ni][1] = -1e30f;
                    if (!(causal ? (gk     <= gq1) : (gk     >= gq1))) sc[ni][2] = -1e30f;
                    if (!(causal ? (gk + 1 <= gq1) : (gk + 1 >= gq1))) sc[ni][3] = -1e30f;
                }
            }

            // online softmax (log2 domain)
            float mt0 = -1e30f, mt1 = -1e30f;
            #pragma unroll
            for (int ni = 0; ni < 8; ni++) {
                mt0 = fmaxf(mt0, fmaxf(sc[ni][0], sc[ni][1]));
                mt1 = fmaxf(mt1, fmaxf(sc[ni][2], sc[ni][3]));
            }
            mt0 = fmaxf(mt0, __shfl_xor_sync(0xffffffffu, mt0, 1));
            mt0 = fmaxf(mt0, __shfl_xor_sync(0xffffffffu, mt0, 2));
            mt1 = fmaxf(mt1, __shfl_xor_sync(0xffffffffu, mt1, 1));
            mt1 = fmaxf(mt1, __shfl_xor_sync(0xffffffffu, mt1, 2));

            float mn0 = fmaxf(m0, mt0), mn1 = fmaxf(m1, mt1);
            float cr0 = ex2(m0 - mn0), cr1 = ex2(m1 - mn1);
            m0 = mn0; m1 = mn1;

            float ls0 = 0.f, ls1 = 0.f;
            #pragma unroll
            for (int ni = 0; ni < 8; ni++) {
                sc[ni][0] = ex2(sc[ni][0] - mn0);
                sc[ni][1] = ex2(sc[ni][1] - mn0);
                sc[ni][2] = ex2(sc[ni][2] - mn1);
                sc[ni][3] = ex2(sc[ni][3] - mn1);
                ls0 += sc[ni][0] + sc[ni][1];
                ls1 += sc[ni][2] + sc[ni][3];
            }
            ls0 += __shfl_xor_sync(0xffffffffu, ls0, 1);
            ls0 += __shfl_xor_sync(0xffffffffu, ls0, 2);
            ls1 += __shfl_xor_sync(0xffffffffu, ls1, 1);
            ls1 += __shfl_xor_sync(0xffffffffu, ls1, 2);
            l0 = l0 * cr0 + ls0;
            l1 = l1 * cr1 + ls1;

            #pragma unroll
            for (int ni = 0; ni < 8; ni++) {
                o[ni][0] *= cr0; o[ni][1] *= cr0;
                o[ni][2] *= cr1; o[ni][3] *= cr1;
            }

            // PV: O += (P_hi + P_lo) * V_hi
            #pragma unroll
            for (int ks = 0; ks < 4; ks++) {
                unsigned ph2[4], pl2[4];
                {
                    __half2 hh, ll;
                    split2v(sc[2*ks][0],   sc[2*ks][1],   hh, ll);
                    ph2[0] = *reinterpret_cast<unsigned*>(&hh);
                    pl2[0] = *reinterpret_cast<unsigned*>(&ll);
                    split2v(sc[2*ks][2],   sc[2*ks][3],   hh, ll);
                    ph2[1] = *reinterpret_cast<unsigned*>(&hh);
                    pl2[1] = *reinterpret_cast<unsigned*>(&ll);
                    split2v(sc[2*ks+1][0], sc[2*ks+1][1], hh, ll);
                    ph2[2] = *reinterpret_cast<unsigned*>(&hh);
                    pl2[2] = *reinterpret_cast<unsigned*>(&ll);
                    split2v(sc[2*ks+1][2], sc[2*ks+1][3], hh, ll);
                    ph2[3] = *reinterpret_cast<unsigned*>(&hh);
                    pl2[3] = *reinterpret_cast<unsigned*>(&ll);
                }
                #pragma unroll
                for (int np = 0; np < 4; np++) {
                    unsigned vh[4];
                    unsigned voff = ((ks * 16 + (lane & 15)) * KSTR
                                     + np * 16 + (lane >> 4) * 8) * 2;
                    ldsm4t(vh, kvb + AVH + voff);
                    mma16(o[2 * np],     ph2, vh[0], vh[1]);
                    mma16(o[2 * np],     pl2, vh[0], vh[1]);
                    mma16(o[2 * np + 1], ph2, vh[2], vh[3]);
                    mma16(o[2 * np + 1], pl2, vh[2], vh[3]);
                }
            }
            __syncthreads();
        }

        // write O as hi/lo fp16 (flat (B,H,N,E))
        float inv0 = 1.f / l0, inv1 = 1.f / l1;
        const size_t ob = ((size_t)b * 16 + h) * NTOK * HDIM;
        #pragma unroll
        for (int ni = 0; ni < 8; ni++) {
            int c = ni * 8 + 2 * quad;
            __half2 h0, l0h, h1, l1h;
            split2v(o[ni][0] * inv0, o[ni][1] * inv0, h0, l0h);
            split2v(o[ni][2] * inv1, o[ni][3] * inv1, h1, l1h);
            size_t i0 = ob + (size_t)gq0 * HDIM + c;
            size_t i1 = ob + (size_t)gq1 * HDIM + c;
            *reinterpret_cast<__half2*>(&Oh[i0]) = h0;
            *reinterpret_cast<__half2*>(&Ol[i0]) = l0h;
            *reinterpret_cast<__half2*>(&Oh[i1]) = h1;
            *reinterpret_cast<__half2*>(&Ol[i1]) = l1h;
        }
    }
}

// ---------------------------------------------------------------------------
extern "C" void kernel_launch(void* const* d_in, const int* in_sizes, int n_in,
                              void* d_out, int out_size) {
    const float* x     = (const float*)d_in[0];
    const float* Wq_lb = (const float*)d_in[1];
    const float* Wk_lb = (const float*)d_in[2];
    const float* Wv_lb = (const float*)d_in[3];
    const float* Wq_la = (const float*)d_in[4];
    const float* Wk_la = (const float*)d_in[5];
    const float* Wv_la = (const float*)d_in[6];
    const float* Wo    = (const float*)d_in[7];

    __half *xh, *xl, *wh, *qkvh, *qkvl, *oh, *ol;
    cudaGetSymbolAddress((void**)&xh, g_xh);
    cudaGetSymbolAddress((void**)&xl, g_xl);
    cudaGetSymbolAddress((void**)&wh, g_wh);
    cudaGetSymbolAddress((void**)&qkvh, g_qkvh);
    cudaGetSymbolAddress((void**)&qkvl, g_qkvl);
    cudaGetSymbolAddress((void**)&oh, g_oh);
    cudaGetSymbolAddress((void**)&ol, g_ol);

    presplit_x<<<4096, 256>>>(x, xh, xl);
    presplit_w<<<4096, 256>>>(Wq_lb, Wq_la, Wk_lb, Wk_la, Wv_lb, Wv_la, Wo, wh);

    cudaFuncSetAttribute(gemm_hl<0>,
                         cudaFuncAttributeMaxDynamicSharedMemorySize, 61440);
    cudaFuncSetAttribute(gemm_hl<1>,
                         cudaFuncAttributeMaxDynamicSharedMemorySize, 61440);
    cudaFuncSetAttribute(attn_hl,
                         cudaFuncAttributeMaxDynamicSharedMemorySize, ATTN_SMEM);

    gemm_hl<0><<<dim3(24, 32), 256, 61440>>>(xh, xl, wh, qkvh, qkvl, nullptr);
    attn_hl<<<dim3(NTOK / 128, NHEAD / 2, BSZ), 256, ATTN_SMEM>>>(qkvh, qkvl,
                                                                  oh, ol);
    gemm_hl<1><<<dim3(8, 32), 256, 61440>>>(oh, ol, wh, nullptr, nullptr,
                                            (float*)d_out);
}